// round 8
// baseline (speedup 1.0000x reference)
#include <cuda_runtime.h>
#include <math.h>

// ---------------- problem constants ----------------
#define BATCH 256
#define DMODEL 512
#define HIDW 1024
#define DA 256
#define DB 256
#define RNK 8
#define NPOOL 2048
#define DPOOL 4608
#define NASP 4
#define DK 64

// output concat layout (floats)
#define OUT0_OFF   ((size_t)0)                       // output: 256*512
#define ALPHA_OFF  ((size_t)131072)                  // alpha: 256*2048
#define W_OFF      ((size_t)655360)                  // W_assembled: 256*65536
#define KEYS_OFF   ((size_t)17432576)                // keys: 2048*256
#define OUT_TOTAL  ((size_t)17956864)

// ---------------- scratch (__device__ globals; no runtime alloc) -------------
__device__ float g_g1[BATCH * HIDW];
__device__ float g_hA[BATCH * DA];
__device__ float g_queries[BATCH * NASP * DK];
__device__ float g_qw[BATCH * NASP * DK];
__device__ float g_kT[NASP * DK * NPOOL];            // k_norm transposed (256 x 2048)
__device__ float g_scores[BATCH * NPOOL];
__device__ float g_alpha[BATCH * NPOOL];
__device__ float g_UV[(size_t)NPOOL * DB * DA];      // 512 MB
__device__ float g_bt[BATCH * DB];
__device__ float g_ht[BATCH * DB];
__device__ float g_hmid[BATCH * DA];
__device__ float g_mid1[BATCH * HIDW];
// fallbacks in case harness output holds only the first tuple element
__device__ float g_keys_fb[NPOOL * NASP * DK];
__device__ float g_W_fb[(size_t)BATCH * DB * DA];

__device__ __forceinline__ float gelu_tanh(float x) {
    float x3 = x * x * x;
    return 0.5f * x * (1.0f + tanhf(0.7978845608028654f * (x + 0.044715f * x3)));
}

// ---------------- generic tiled SGEMM: C = act(A@B + bias) ----------------
// A: M x K (lda), B: K x N (ldb), C: M x N (ldc). Batched via blockIdx.z strides.
__global__ void __launch_bounds__(256) gemm64(
    const float* __restrict__ A, int lda, size_t sA,
    const float* __restrict__ Bm, int ldb, size_t sB,
    float* __restrict__ C, int ldc, size_t sC,
    int M, int N, int K,
    const float* __restrict__ bias, int act)
{
    __shared__ float As[8][64];
    __shared__ float Bs[8][64];
    int z = blockIdx.z;
    A  += (size_t)z * sA;
    Bm += (size_t)z * sB;
    C  += (size_t)z * sC;
    int bm = blockIdx.y * 64, bn = blockIdx.x * 64;
    int tid = threadIdx.x;
    int aRow = tid >> 2, aCol = (tid & 3) * 2;
    int bRow = tid >> 5, bCol = (tid & 31) * 2;
    int ty = tid >> 4, tx = tid & 15;
    float acc[4][4] = {};
    for (int k0 = 0; k0 < K; k0 += 8) {
        int gm = bm + aRow;
        #pragma unroll
        for (int i = 0; i < 2; i++) {
            int gk = k0 + aCol + i;
            As[aCol + i][aRow] = (gm < M && gk < K) ? A[(size_t)gm * lda + gk] : 0.0f;
        }
        int gk2 = k0 + bRow;
        #pragma unroll
        for (int j = 0; j < 2; j++) {
            int gn = bn + bCol + j;
            Bs[bRow][bCol + j] = (gk2 < K && gn < N) ? Bm[(size_t)gk2 * ldb + gn] : 0.0f;
        }
        __syncthreads();
        #pragma unroll
        for (int k = 0; k < 8; k++) {
            float ra[4], rb[4];
            #pragma unroll
            for (int i = 0; i < 4; i++) ra[i] = As[k][ty * 4 + i];
            #pragma unroll
            for (int j = 0; j < 4; j++) rb[j] = Bs[k][tx * 4 + j];
            #pragma unroll
            for (int i = 0; i < 4; i++)
                #pragma unroll
                for (int j = 0; j < 4; j++)
                    acc[i][j] += ra[i] * rb[j];
        }
        __syncthreads();
    }
    #pragma unroll
    for (int i = 0; i < 4; i++) {
        int gm = bm + ty * 4 + i;
        if (gm >= M) continue;
        #pragma unroll
        for (int j = 0; j < 4; j++) {
            int gn = bn + tx * 4 + j;
            if (gn >= N) continue;
            float v = acc[i][j];
            if (bias) v += bias[gn];
            if (act == 1) v = gelu_tanh(v);
            C[(size_t)gm * ldc + gn] = v;
        }
    }
}

// ---------------- main GEMM: W = alpha(256x2048) @ UV(2048x65536) + W_base ---
// 128x128 block tile, BK=8, 256 threads, 8x8 per thread.
__global__ void __launch_bounds__(256) wgemm(
    const float* __restrict__ A,    // 256 x 2048
    const float* __restrict__ Bm,   // 2048 x 65536
    const float* __restrict__ Wb,   // 65536
    float* __restrict__ C)          // 256 x 65536
{
    const int N = DB * DA;          // 65536
    const int K = NPOOL;            // 2048
    __shared__ float As[8][128];
    __shared__ float Bs[8][128];
    int bn = blockIdx.x * 128;
    int bm = blockIdx.y * 128;
    int tid = threadIdx.x;
    int aRow = tid >> 1;            // 0..127
    int aCol = (tid & 1) * 4;       // 0 or 4
    int bRow = tid >> 5;            // 0..7
    int bCol = (tid & 31) * 4;      // 0..124
    int tRow = (tid >> 4) * 8;      // 0..120
    int tCol = (tid & 15) * 8;      // 0..120
    float acc[8][8] = {};
    const float* Aptr = A + (size_t)(bm + aRow) * K + aCol;
    const float* Bptr = Bm + (size_t)bRow * N + bn + bCol;
    for (int k0 = 0; k0 < K; k0 += 8) {
        float4 av = *(const float4*)Aptr;
        As[aCol + 0][aRow] = av.x;
        As[aCol + 1][aRow] = av.y;
        As[aCol + 2][aRow] = av.z;
        As[aCol + 3][aRow] = av.w;
        *(float4*)&Bs[bRow][bCol] = *(const float4*)Bptr;
        __syncthreads();
        #pragma unroll
        for (int k = 0; k < 8; k++) {
            float ra[8], rb[8];
            *(float4*)(ra)     = *(const float4*)&As[k][tRow];
            *(float4*)(ra + 4) = *(const float4*)&As[k][tRow + 4];
            *(float4*)(rb)     = *(const float4*)&Bs[k][tCol];
            *(float4*)(rb + 4) = *(const float4*)&Bs[k][tCol + 4];
            #pragma unroll
            for (int i = 0; i < 8; i++)
                #pragma unroll
                for (int j = 0; j < 8; j++)
                    acc[i][j] += ra[i] * rb[j];
        }
        __syncthreads();
        Aptr += 8;
        Bptr += (size_t)8 * N;
    }
    float wb[8];
    #pragma unroll
    for (int j = 0; j < 8; j++) wb[j] = Wb[bn + tCol + j];
    #pragma unroll
    for (int i = 0; i < 8; i++) {
        float* crow = C + (size_t)(bm + tRow + i) * N + bn + tCol;
        float4 c0, c1;
        c0.x = acc[i][0] + wb[0]; c0.y = acc[i][1] + wb[1];
        c0.z = acc[i][2] + wb[2]; c0.w = acc[i][3] + wb[3];
        c1.x = acc[i][4] + wb[4]; c1.y = acc[i][5] + wb[5];
        c1.z = acc[i][6] + wb[6]; c1.w = acc[i][7] + wb[7];
        *(float4*)crow       = c0;
        *(float4*)(crow + 4) = c1;
    }
}

// ---------------- q normalization + aspect weighting ----------------
__global__ void qnorm_kernel(const float* __restrict__ q,
                             const float* __restrict__ logits,
                             float* __restrict__ qw)
{
    int b = blockIdx.x;
    int wid = threadIdx.x >> 5, lane = threadIdx.x & 31;
    float l[4];
    #pragma unroll
    for (int a = 0; a < 4; a++) l[a] = logits[a];
    float mx = fmaxf(fmaxf(l[0], l[1]), fmaxf(l[2], l[3]));
    float e[4], sum = 0.0f;
    #pragma unroll
    for (int a = 0; a < 4; a++) { e[a] = expf(l[a] - mx); sum += e[a]; }
    float w = e[wid] / sum;

    const float* row = q + (size_t)b * 256 + wid * 64;
    float v0 = row[lane], v1 = row[lane + 32];
    float ss = v0 * v0 + v1 * v1;
    #pragma unroll
    for (int o = 16; o > 0; o >>= 1) ss += __shfl_xor_sync(0xffffffffu, ss, o);
    float scale = w / (sqrtf(ss) + 1e-8f);
    float* orow = qw + (size_t)b * 256 + wid * 64;
    orow[lane] = v0 * scale;
    orow[lane + 32] = v1 * scale;
}

// ---------------- k normalization, write transposed (256 x 2048) ------------
__global__ void knorm_kernel(const float* __restrict__ keys,
                             float* __restrict__ kT)
{
    int n = blockIdx.x;
    int wid = threadIdx.x >> 5, lane = threadIdx.x & 31;
    const float* row = keys + (size_t)n * 256 + wid * 64;
    float v0 = row[lane], v1 = row[lane + 32];
    float ss = v0 * v0 + v1 * v1;
    #pragma unroll
    for (int o = 16; o > 0; o >>= 1) ss += __shfl_xor_sync(0xffffffffu, ss, o);
    float inv = 1.0f / (sqrtf(ss) + 1e-8f);
    kT[(size_t)(wid * 64 + lane) * NPOOL + n]      = v0 * inv;
    kT[(size_t)(wid * 64 + lane + 32) * NPOOL + n] = v1 * inv;
}

// ---------------- alpha = normalize(sigmoid(s - tau) * exp(s)) --------------
__global__ void alpha_kernel(const float* __restrict__ scores,
                             const float* __restrict__ tau_p,
                             float* __restrict__ alpha_s,
                             float* __restrict__ alpha_o)
{
    int b = blockIdx.x, tid = threadIdx.x;
    float tau = tau_p[0];
    float ar[8], s = 0.0f;
    #pragma unroll
    for (int i = 0; i < 8; i++) {
        int n = tid + i * 256;
        float sc = scores[(size_t)b * NPOOL + n];
        float g = 1.0f / (1.0f + expf(-(sc - tau)));
        float a = g * expf(sc);
        ar[i] = a;
        s += a;
    }
    __shared__ float red[256];
    red[tid] = s;
    __syncthreads();
    for (int o = 128; o > 0; o >>= 1) {
        if (tid < o) red[tid] += red[tid + o];
        __syncthreads();
    }
    float inv = 1.0f / (red[0] + 1e-8f);
    #pragma unroll
    for (int i = 0; i < 8; i++) {
        int n = tid + i * 256;
        float v = ar[i] * inv;
        alpha_s[(size_t)b * NPOOL + n] = v;
        if (alpha_o != alpha_s) alpha_o[(size_t)b * NPOOL + n] = v;
    }
}

// ---------------- UV[n] = U(256x8) @ V(8x256) from pool row -----------------
__global__ void __launch_bounds__(256) uv_kernel(const float* __restrict__ pool,
                                                 float* __restrict__ UV)
{
    __shared__ float sm[4096];
    int n = blockIdx.x, tid = threadIdx.x;
    const float* prow = pool + (size_t)n * DPOOL;
    #pragma unroll
    for (int i = 0; i < 16; i++) sm[tid + i * 256] = prow[tid + i * 256];
    __syncthreads();
    float v[8];
    #pragma unroll
    for (int r = 0; r < 8; r++) v[r] = sm[2048 + r * 256 + tid];
    float* out = UV + (size_t)n * 65536 + tid;
    #pragma unroll 4
    for (int d = 0; d < 256; d++) {
        float acc = 0.0f;
        #pragma unroll
        for (int r = 0; r < 8; r++) acc += sm[d * 8 + r] * v[r];
        out[(size_t)d * 256] = acc;
    }
}

// ---------------- h_t[b,c] = dot(W_assembled[b,c,:], h_A[b,:]) --------------
__global__ void __launch_bounds__(256) ht_kernel(const float* __restrict__ W,
                                                 const float* __restrict__ hA,
                                                 float* __restrict__ ht)
{
    int b = blockIdx.x;
    int wid = threadIdx.x >> 5, lane = threadIdx.x & 31;
    __shared__ float ha[256];
    ha[threadIdx.x] = hA[(size_t)b * 256 + threadIdx.x];
    __syncthreads();
    for (int c = wid; c < 256; c += 8) {
        const float* wrow = W + (size_t)b * 65536 + (size_t)c * 256;
        float s = 0.0f;
        #pragma unroll
        for (int j = 0; j < 8; j++) {
            int a = lane + j * 32;
            s += wrow[a] * ha[a];
        }
        #pragma unroll
        for (int o = 16; o > 0; o >>= 1) s += __shfl_xor_sync(0xffffffffu, s, o);
        if (lane == 0) ht[(size_t)b * 256 + c] = s;
    }
}

// ---------------- y = hA + gamma*(ht + b_asm); LayerNorm -> hmid ------------
__global__ void ln_kernel(const float* __restrict__ hA,
                          const float* __restrict__ ht,
                          const float* __restrict__ bt,
                          const float* __restrict__ gamma_p,
                          const float* __restrict__ ln_s,
                          const float* __restrict__ ln_b,
                          float* __restrict__ hmid)
{
    int b = blockIdx.x, c = threadIdx.x;
    float g = gamma_p[0];
    size_t idx = (size_t)b * 256 + c;
    float y = hA[idx] + g * (ht[idx] + bt[idx]);
    __shared__ float red[256];
    red[c] = y;
    __syncthreads();
    for (int o = 128; o > 0; o >>= 1) {
        if (c < o) red[c] += red[c + o];
        __syncthreads();
    }
    float mu = red[0] * (1.0f / 256.0f);
    __syncthreads();
    float d = y - mu;
    red[c] = d * d;
    __syncthreads();
    for (int o = 128; o > 0; o >>= 1) {
        if (c < o) red[c] += red[c + o];
        __syncthreads();
    }
    float var = red[0] * (1.0f / 256.0f);
    hmid[idx] = d * rsqrtf(var + 1e-6f) * ln_s[c] + ln_b[c];
}

// ---------------- launch ----------------
extern "C" void kernel_launch(void* const* d_in, const int* in_sizes, int n_in,
                              void* d_out, int out_size)
{
    (void)in_sizes; (void)n_in;
    const float* x        = (const float*)d_in[0];
    const float* pool     = (const float*)d_in[1];
    const float* A_w0     = (const float*)d_in[2];
    const float* A_b0     = (const float*)d_in[3];
    const float* A_w1     = (const float*)d_in[4];
    const float* A_b1     = (const float*)d_in[5];
    const float* W_Q      = (const float*)d_in[6];
    const float* W_K      = (const float*)d_in[7];
    const float* logits   = (const float*)d_in[8];
    const float* tau      = (const float*)d_in[9];
    const float* W_base   = (const float*)d_in[10];
    const float* b_base   = (const float*)d_in[11];
    const float* gamma    = (const float*)d_in[12];
    const float* ln_scale = (const float*)d_in[13];
    const float* ln_bias  = (const float*)d_in[14];
    const float* B_w0     = (const float*)d_in[15];
    const float* B_b0     = (const float*)d_in[16];
    const float* B_w1     = (const float*)d_in[17];
    const float* B_b1     = (const float*)d_in[18];
    float* out = (float*)d_out;

    // device-symbol scratch addresses
    float *p_g1, *p_hA, *p_q, *p_qw, *p_kT, *p_sc, *p_al, *p_UV, *p_bt, *p_ht,
          *p_hmid, *p_mid1, *p_keys_fb, *p_W_fb;
    cudaGetSymbolAddress((void**)&p_g1, g_g1);
    cudaGetSymbolAddress((void**)&p_hA, g_hA);
    cudaGetSymbolAddress((void**)&p_q, g_queries);
    cudaGetSymbolAddress((void**)&p_qw, g_qw);
    cudaGetSymbolAddress((void**)&p_kT, g_kT);
    cudaGetSymbolAddress((void**)&p_sc, g_scores);
    cudaGetSymbolAddress((void**)&p_al, g_alpha);
    cudaGetSymbolAddress((void**)&p_UV, g_UV);
    cudaGetSymbolAddress((void**)&p_bt, g_bt);
    cudaGetSymbolAddress((void**)&p_ht, g_ht);
    cudaGetSymbolAddress((void**)&p_hmid, g_hmid);
    cudaGetSymbolAddress((void**)&p_mid1, g_mid1);
    cudaGetSymbolAddress((void**)&p_keys_fb, g_keys_fb);
    cudaGetSymbolAddress((void**)&p_W_fb, g_W_fb);

    bool full = ((size_t)out_size >= OUT_TOTAL);
    float* out0     = out + OUT0_OFF;
    float* out_al   = full ? out + ALPHA_OFF : p_al;
    float* out_W    = full ? out + W_OFF     : p_W_fb;
    float* out_keys = full ? out + KEYS_OFF  : p_keys_fb;

    // 1) g1 = gelu(x @ A_w0 + A_b0)         (256x1024, K=512)
    gemm64<<<dim3(16, 4, 1), 256>>>(x, DMODEL, 0, A_w0, HIDW, 0,
                                    p_g1, HIDW, 0, BATCH, HIDW, DMODEL, A_b0, 1);
    // 2) h_A = g1 @ A_w1 + A_b1             (256x256, K=1024)
    gemm64<<<dim3(4, 4, 1), 256>>>(p_g1, HIDW, 0, A_w1, DA, 0,
                                   p_hA, DA, 0, BATCH, DA, HIDW, A_b1, 0);
    // 3) queries[b, a*64+q] : 4 batched GEMMs M=256,N=64,K=256
    gemm64<<<dim3(1, 4, NASP), 256>>>(p_hA, DA, 0, W_Q, DK, (size_t)DA * DK,
                                      p_q, DA, DK, BATCH, DK, DA, nullptr, 0);
    // 4) keys: 4 batched GEMMs M=2048,N=64,K=4608 -> out_keys
    gemm64<<<dim3(1, 32, NASP), 256>>>(pool, DPOOL, 0, W_K, DK, (size_t)DPOOL * DK,
                                       out_keys, DA, DK, NPOOL, DK, DPOOL, nullptr, 0);
    // 5) q_norm * softmax(aspect_logits)
    qnorm_kernel<<<BATCH, 128>>>(p_q, logits, p_qw);
    // 6) k_norm transposed
    knorm_kernel<<<NPOOL, 128>>>(out_keys, p_kT);
    // 7) scores = qw @ kT                   (256x2048, K=256)
    gemm64<<<dim3(32, 4, 1), 256>>>(p_qw, DA, 0, p_kT, NPOOL, 0,
                                    p_sc, NPOOL, 0, BATCH, NPOOL, DA, nullptr, 0);
    // 8) alpha
    alpha_kernel<<<BATCH, 256>>>(p_sc, tau, p_al, out_al);
    // 9) UV[n] = U @ V
    uv_kernel<<<NPOOL, 256>>>(pool, p_UV);
    // 10) b_assembled = alpha @ bias(pool cols 4096:4352) + b_base
    gemm64<<<dim3(4, 4, 1), 256>>>(p_al, NPOOL, 0, pool + 4096, DPOOL, 0,
                                   p_bt, DB, 0, BATCH, DB, NPOOL, b_base, 0);
    // 11) W_assembled = alpha @ UV + W_base  (the big one: 68.7 GFLOP)
    wgemm<<<dim3(512, 2, 1), 256>>>(p_al, p_UV, W_base, out_W);
    // 12) h_t = einsum('ba,bca->bc', hA, W_assembled)
    ht_kernel<<<BATCH, 256>>>(out_W, p_hA, p_ht);
    // 13) y + LayerNorm -> hmid
    ln_kernel<<<BATCH, 256>>>(p_hA, p_ht, p_bt, gamma, ln_scale, ln_bias, p_hmid);
    // 14) mid1 = gelu(hmid @ B_w0 + B_b0)   (256x1024, K=256)
    gemm64<<<dim3(16, 4, 1), 256>>>(p_hmid, DA, 0, B_w0, HIDW, 0,
                                    p_mid1, HIDW, 0, BATCH, HIDW, DA, B_b0, 1);
    // 15) output = mid1 @ B_w1 + B_b1       (256x512, K=1024)
    gemm64<<<dim3(8, 4, 1), 256>>>(p_mid1, HIDW, 0, B_w1, DMODEL, 0,
                                   out0, DMODEL, 0, BATCH, DMODEL, HIDW, B_b1, 0);
}

// round 9
// speedup vs baseline: 1.0004x; 1.0004x over previous
#include <cuda_runtime.h>
#include <math.h>

// ---------------- problem constants ----------------
#define BATCH 256
#define DMODEL 512
#define HIDW 1024
#define DA 256
#define DB 256
#define RNK 8
#define NPOOL 2048
#define DPOOL 4608
#define NASP 4
#define DK 64

// output concat layout (floats)
#define OUT0_OFF   ((size_t)0)                       // output: 256*512
#define ALPHA_OFF  ((size_t)131072)                  // alpha: 256*2048
#define W_OFF      ((size_t)655360)                  // W_assembled: 256*65536
#define KEYS_OFF   ((size_t)17432576)                // keys: 2048*256
#define OUT_TOTAL  ((size_t)17956864)

// ---------------- scratch (__device__ globals; no runtime alloc) -------------
__device__ float g_g1[BATCH * HIDW];
__device__ float g_hA[BATCH * DA];
__device__ float g_queries[BATCH * NASP * DK];
__device__ float g_qw[BATCH * NASP * DK];
__device__ float g_kT[NASP * DK * NPOOL];            // k_norm transposed (256 x 2048)
__device__ float g_scores[BATCH * NPOOL];
__device__ float g_alpha[BATCH * NPOOL];
__device__ float g_UV[(size_t)NPOOL * DB * DA];      // 512 MB
__device__ float g_bt[BATCH * DB];
__device__ float g_ht[BATCH * DB];
__device__ float g_hmid[BATCH * DA];
__device__ float g_mid1[BATCH * HIDW];
// fallbacks in case harness output holds only the first tuple element
__device__ float g_keys_fb[NPOOL * NASP * DK];
__device__ float g_W_fb[(size_t)BATCH * DB * DA];

__device__ __forceinline__ float gelu_tanh(float x) {
    float x3 = x * x * x;
    return 0.5f * x * (1.0f + tanhf(0.7978845608028654f * (x + 0.044715f * x3)));
}

// ---------------- generic tiled SGEMM: C = act(A@B + bias) ----------------
// A: M x K (lda), B: K x N (ldb), C: M x N (ldc). Batched via blockIdx.z strides.
__global__ void __launch_bounds__(256) gemm64(
    const float* __restrict__ A, int lda, size_t sA,
    const float* __restrict__ Bm, int ldb, size_t sB,
    float* __restrict__ C, int ldc, size_t sC,
    int M, int N, int K,
    const float* __restrict__ bias, int act)
{
    __shared__ float As[8][64];
    __shared__ float Bs[8][64];
    int z = blockIdx.z;
    A  += (size_t)z * sA;
    Bm += (size_t)z * sB;
    C  += (size_t)z * sC;
    int bm = blockIdx.y * 64, bn = blockIdx.x * 64;
    int tid = threadIdx.x;
    int aRow = tid >> 2, aCol = (tid & 3) * 2;
    int bRow = tid >> 5, bCol = (tid & 31) * 2;
    int ty = tid >> 4, tx = tid & 15;
    float acc[4][4] = {};
    for (int k0 = 0; k0 < K; k0 += 8) {
        int gm = bm + aRow;
        #pragma unroll
        for (int i = 0; i < 2; i++) {
            int gk = k0 + aCol + i;
            As[aCol + i][aRow] = (gm < M && gk < K) ? A[(size_t)gm * lda + gk] : 0.0f;
        }
        int gk2 = k0 + bRow;
        #pragma unroll
        for (int j = 0; j < 2; j++) {
            int gn = bn + bCol + j;
            Bs[bRow][bCol + j] = (gk2 < K && gn < N) ? Bm[(size_t)gk2 * ldb + gn] : 0.0f;
        }
        __syncthreads();
        #pragma unroll
        for (int k = 0; k < 8; k++) {
            float ra[4], rb[4];
            #pragma unroll
            for (int i = 0; i < 4; i++) ra[i] = As[k][ty * 4 + i];
            #pragma unroll
            for (int j = 0; j < 4; j++) rb[j] = Bs[k][tx * 4 + j];
            #pragma unroll
            for (int i = 0; i < 4; i++)
                #pragma unroll
                for (int j = 0; j < 4; j++)
                    acc[i][j] += ra[i] * rb[j];
        }
        __syncthreads();
    }
    #pragma unroll
    for (int i = 0; i < 4; i++) {
        int gm = bm + ty * 4 + i;
        if (gm >= M) continue;
        #pragma unroll
        for (int j = 0; j < 4; j++) {
            int gn = bn + tx * 4 + j;
            if (gn >= N) continue;
            float v = acc[i][j];
            if (bias) v += bias[gn];
            if (act == 1) v = gelu_tanh(v);
            C[(size_t)gm * ldc + gn] = v;
        }
    }
}

// ---------------- main GEMM: W = alpha(256x2048) @ UV(2048x65536) + W_base ---
// 128x128 block tile, BK=8, 256 threads, 8x8 per thread.
__global__ void __launch_bounds__(256) wgemm(
    const float* __restrict__ A,    // 256 x 2048
    const float* __restrict__ Bm,   // 2048 x 65536
    const float* __restrict__ Wb,   // 65536
    float* __restrict__ C)          // 256 x 65536
{
    const int N = DB * DA;          // 65536
    const int K = NPOOL;            // 2048
    __shared__ float As[8][128];
    __shared__ float Bs[8][128];
    int bn = blockIdx.x * 128;
    int bm = blockIdx.y * 128;
    int tid = threadIdx.x;
    int aRow = tid >> 1;            // 0..127
    int aCol = (tid & 1) * 4;       // 0 or 4
    int bRow = tid >> 5;            // 0..7
    int bCol = (tid & 31) * 4;      // 0..124
    int tRow = (tid >> 4) * 8;      // 0..120
    int tCol = (tid & 15) * 8;      // 0..120
    float acc[8][8] = {};
    const float* Aptr = A + (size_t)(bm + aRow) * K + aCol;
    const float* Bptr = Bm + (size_t)bRow * N + bn + bCol;
    for (int k0 = 0; k0 < K; k0 += 8) {
        float4 av = *(const float4*)Aptr;
        As[aCol + 0][aRow] = av.x;
        As[aCol + 1][aRow] = av.y;
        As[aCol + 2][aRow] = av.z;
        As[aCol + 3][aRow] = av.w;
        *(float4*)&Bs[bRow][bCol] = *(const float4*)Bptr;
        __syncthreads();
        #pragma unroll
        for (int k = 0; k < 8; k++) {
            float ra[8], rb[8];
            *(float4*)(ra)     = *(const float4*)&As[k][tRow];
            *(float4*)(ra + 4) = *(const float4*)&As[k][tRow + 4];
            *(float4*)(rb)     = *(const float4*)&Bs[k][tCol];
            *(float4*)(rb + 4) = *(const float4*)&Bs[k][tCol + 4];
            #pragma unroll
            for (int i = 0; i < 8; i++)
                #pragma unroll
                for (int j = 0; j < 8; j++)
                    acc[i][j] += ra[i] * rb[j];
        }
        __syncthreads();
        Aptr += 8;
        Bptr += (size_t)8 * N;
    }
    float wb[8];
    #pragma unroll
    for (int j = 0; j < 8; j++) wb[j] = Wb[bn + tCol + j];
    #pragma unroll
    for (int i = 0; i < 8; i++) {
        float* crow = C + (size_t)(bm + tRow + i) * N + bn + tCol;
        float4 c0, c1;
        c0.x = acc[i][0] + wb[0]; c0.y = acc[i][1] + wb[1];
        c0.z = acc[i][2] + wb[2]; c0.w = acc[i][3] + wb[3];
        c1.x = acc[i][4] + wb[4]; c1.y = acc[i][5] + wb[5];
        c1.z = acc[i][6] + wb[6]; c1.w = acc[i][7] + wb[7];
        *(float4*)crow       = c0;
        *(float4*)(crow + 4) = c1;
    }
}

// ---------------- q normalization + aspect weighting ----------------
__global__ void qnorm_kernel(const float* __restrict__ q,
                             const float* __restrict__ logits,
                             float* __restrict__ qw)
{
    int b = blockIdx.x;
    int wid = threadIdx.x >> 5, lane = threadIdx.x & 31;
    float l[4];
    #pragma unroll
    for (int a = 0; a < 4; a++) l[a] = logits[a];
    float mx = fmaxf(fmaxf(l[0], l[1]), fmaxf(l[2], l[3]));
    float e[4], sum = 0.0f;
    #pragma unroll
    for (int a = 0; a < 4; a++) { e[a] = expf(l[a] - mx); sum += e[a]; }
    float w = e[wid] / sum;

    const float* row = q + (size_t)b * 256 + wid * 64;
    float v0 = row[lane], v1 = row[lane + 32];
    float ss = v0 * v0 + v1 * v1;
    #pragma unroll
    for (int o = 16; o > 0; o >>= 1) ss += __shfl_xor_sync(0xffffffffu, ss, o);
    float scale = w / (sqrtf(ss) + 1e-8f);
    float* orow = qw + (size_t)b * 256 + wid * 64;
    orow[lane] = v0 * scale;
    orow[lane + 32] = v1 * scale;
}

// ---------------- k normalization, write transposed (256 x 2048) ------------
__global__ void knorm_kernel(const float* __restrict__ keys,
                             float* __restrict__ kT)
{
    int n = blockIdx.x;
    int wid = threadIdx.x >> 5, lane = threadIdx.x & 31;
    const float* row = keys + (size_t)n * 256 + wid * 64;
    float v0 = row[lane], v1 = row[lane + 32];
    float ss = v0 * v0 + v1 * v1;
    #pragma unroll
    for (int o = 16; o > 0; o >>= 1) ss += __shfl_xor_sync(0xffffffffu, ss, o);
    float inv = 1.0f / (sqrtf(ss) + 1e-8f);
    kT[(size_t)(wid * 64 + lane) * NPOOL + n]      = v0 * inv;
    kT[(size_t)(wid * 64 + lane + 32) * NPOOL + n] = v1 * inv;
}

// ---------------- alpha = normalize(sigmoid(s - tau) * exp(s)) --------------
__global__ void alpha_kernel(const float* __restrict__ scores,
                             const float* __restrict__ tau_p,
                             float* __restrict__ alpha_s,
                             float* __restrict__ alpha_o)
{
    int b = blockIdx.x, tid = threadIdx.x;
    float tau = tau_p[0];
    float ar[8], s = 0.0f;
    #pragma unroll
    for (int i = 0; i < 8; i++) {
        int n = tid + i * 256;
        float sc = scores[(size_t)b * NPOOL + n];
        float g = 1.0f / (1.0f + expf(-(sc - tau)));
        float a = g * expf(sc);
        ar[i] = a;
        s += a;
    }
    __shared__ float red[256];
    red[tid] = s;
    __syncthreads();
    for (int o = 128; o > 0; o >>= 1) {
        if (tid < o) red[tid] += red[tid + o];
        __syncthreads();
    }
    float inv = 1.0f / (red[0] + 1e-8f);
    #pragma unroll
    for (int i = 0; i < 8; i++) {
        int n = tid + i * 256;
        float v = ar[i] * inv;
        alpha_s[(size_t)b * NPOOL + n] = v;
        if (alpha_o != alpha_s) alpha_o[(size_t)b * NPOOL + n] = v;
    }
}

// ---------------- UV[n] = U(256x8) @ V(8x256) from pool row -----------------
__global__ void __launch_bounds__(256) uv_kernel(const float* __restrict__ pool,
                                                 float* __restrict__ UV)
{
    __shared__ float sm[4096];
    int n = blockIdx.x, tid = threadIdx.x;
    const float* prow = pool + (size_t)n * DPOOL;
    #pragma unroll
    for (int i = 0; i < 16; i++) sm[tid + i * 256] = prow[tid + i * 256];
    __syncthreads();
    float v[8];
    #pragma unroll
    for (int r = 0; r < 8; r++) v[r] = sm[2048 + r * 256 + tid];
    float* out = UV + (size_t)n * 65536 + tid;
    #pragma unroll 4
    for (int d = 0; d < 256; d++) {
        float acc = 0.0f;
        #pragma unroll
        for (int r = 0; r < 8; r++) acc += sm[d * 8 + r] * v[r];
        out[(size_t)d * 256] = acc;
    }
}

// ---------------- h_t[b,c] = dot(W_assembled[b,c,:], h_A[b,:]) --------------
__global__ void __launch_bounds__(256) ht_kernel(const float* __restrict__ W,
                                                 const float* __restrict__ hA,
                                                 float* __restrict__ ht)
{
    int b = blockIdx.x;
    int wid = threadIdx.x >> 5, lane = threadIdx.x & 31;
    __shared__ float ha[256];
    ha[threadIdx.x] = hA[(size_t)b * 256 + threadIdx.x];
    __syncthreads();
    for (int c = wid; c < 256; c += 8) {
        const float* wrow = W + (size_t)b * 65536 + (size_t)c * 256;
        float s = 0.0f;
        #pragma unroll
        for (int j = 0; j < 8; j++) {
            int a = lane + j * 32;
            s += wrow[a] * ha[a];
        }
        #pragma unroll
        for (int o = 16; o > 0; o >>= 1) s += __shfl_xor_sync(0xffffffffu, s, o);
        if (lane == 0) ht[(size_t)b * 256 + c] = s;
    }
}

// ---------------- y = hA + gamma*(ht + b_asm); LayerNorm -> hmid ------------
__global__ void ln_kernel(const float* __restrict__ hA,
                          const float* __restrict__ ht,
                          const float* __restrict__ bt,
                          const float* __restrict__ gamma_p,
                          const float* __restrict__ ln_s,
                          const float* __restrict__ ln_b,
                          float* __restrict__ hmid)
{
    int b = blockIdx.x, c = threadIdx.x;
    float g = gamma_p[0];
    size_t idx = (size_t)b * 256 + c;
    float y = hA[idx] + g * (ht[idx] + bt[idx]);
    __shared__ float red[256];
    red[c] = y;
    __syncthreads();
    for (int o = 128; o > 0; o >>= 1) {
        if (c < o) red[c] += red[c + o];
        __syncthreads();
    }
    float mu = red[0] * (1.0f / 256.0f);
    __syncthreads();
    float d = y - mu;
    red[c] = d * d;
    __syncthreads();
    for (int o = 128; o > 0; o >>= 1) {
        if (c < o) red[c] += red[c + o];
        __syncthreads();
    }
    float var = red[0] * (1.0f / 256.0f);
    hmid[idx] = d * rsqrtf(var + 1e-6f) * ln_s[c] + ln_b[c];
}

// ---------------- launch ----------------
extern "C" void kernel_launch(void* const* d_in, const int* in_sizes, int n_in,
                              void* d_out, int out_size)
{
    (void)in_sizes; (void)n_in;
    const float* x        = (const float*)d_in[0];
    const float* pool     = (const float*)d_in[1];
    const float* A_w0     = (const float*)d_in[2];
    const float* A_b0     = (const float*)d_in[3];
    const float* A_w1     = (const float*)d_in[4];
    const float* A_b1     = (const float*)d_in[5];
    const float* W_Q      = (const float*)d_in[6];
    const float* W_K      = (const float*)d_in[7];
    const float* logits   = (const float*)d_in[8];
    const float* tau      = (const float*)d_in[9];
    const float* W_base   = (const float*)d_in[10];
    const float* b_base   = (const float*)d_in[11];
    const float* gamma    = (const float*)d_in[12];
    const float* ln_scale = (const float*)d_in[13];
    const float* ln_bias  = (const float*)d_in[14];
    const float* B_w0     = (const float*)d_in[15];
    const float* B_b0     = (const float*)d_in[16];
    const float* B_w1     = (const float*)d_in[17];
    const float* B_b1     = (const float*)d_in[18];
    float* out = (float*)d_out;

    // device-symbol scratch addresses
    float *p_g1, *p_hA, *p_q, *p_qw, *p_kT, *p_sc, *p_al, *p_UV, *p_bt, *p_ht,
          *p_hmid, *p_mid1, *p_keys_fb, *p_W_fb;
    cudaGetSymbolAddress((void**)&p_g1, g_g1);
    cudaGetSymbolAddress((void**)&p_hA, g_hA);
    cudaGetSymbolAddress((void**)&p_q, g_queries);
    cudaGetSymbolAddress((void**)&p_qw, g_qw);
    cudaGetSymbolAddress((void**)&p_kT, g_kT);
    cudaGetSymbolAddress((void**)&p_sc, g_scores);
    cudaGetSymbolAddress((void**)&p_al, g_alpha);
    cudaGetSymbolAddress((void**)&p_UV, g_UV);
    cudaGetSymbolAddress((void**)&p_bt, g_bt);
    cudaGetSymbolAddress((void**)&p_ht, g_ht);
    cudaGetSymbolAddress((void**)&p_hmid, g_hmid);
    cudaGetSymbolAddress((void**)&p_mid1, g_mid1);
    cudaGetSymbolAddress((void**)&p_keys_fb, g_keys_fb);
    cudaGetSymbolAddress((void**)&p_W_fb, g_W_fb);

    bool full = ((size_t)out_size >= OUT_TOTAL);
    float* out0     = out + OUT0_OFF;
    float* out_al   = full ? out + ALPHA_OFF : p_al;
    float* out_W    = full ? out + W_OFF     : p_W_fb;
    float* out_keys = full ? out + KEYS_OFF  : p_keys_fb;

    // 1) g1 = gelu(x @ A_w0 + A_b0)         (256x1024, K=512)
    gemm64<<<dim3(16, 4, 1), 256>>>(x, DMODEL, 0, A_w0, HIDW, 0,
                                    p_g1, HIDW, 0, BATCH, HIDW, DMODEL, A_b0, 1);
    // 2) h_A = g1 @ A_w1 + A_b1             (256x256, K=1024)
    gemm64<<<dim3(4, 4, 1), 256>>>(p_g1, HIDW, 0, A_w1, DA, 0,
                                   p_hA, DA, 0, BATCH, DA, HIDW, A_b1, 0);
    // 3) queries[b, a*64+q] : 4 batched GEMMs M=256,N=64,K=256
    gemm64<<<dim3(1, 4, NASP), 256>>>(p_hA, DA, 0, W_Q, DK, (size_t)DA * DK,
                                      p_q, DA, DK, BATCH, DK, DA, nullptr, 0);
    // 4) keys: 4 batched GEMMs M=2048,N=64,K=4608 -> out_keys
    gemm64<<<dim3(1, 32, NASP), 256>>>(pool, DPOOL, 0, W_K, DK, (size_t)DPOOL * DK,
                                       out_keys, DA, DK, NPOOL, DK, DPOOL, nullptr, 0);
    // 5) q_norm * softmax(aspect_logits)
    qnorm_kernel<<<BATCH, 128>>>(p_q, logits, p_qw);
    // 6) k_norm transposed
    knorm_kernel<<<NPOOL, 128>>>(out_keys, p_kT);
    // 7) scores = qw @ kT                   (256x2048, K=256)
    gemm64<<<dim3(32, 4, 1), 256>>>(p_qw, DA, 0, p_kT, NPOOL, 0,
                                    p_sc, NPOOL, 0, BATCH, NPOOL, DA, nullptr, 0);
    // 8) alpha
    alpha_kernel<<<BATCH, 256>>>(p_sc, tau, p_al, out_al);
    // 9) UV[n] = U @ V
    uv_kernel<<<NPOOL, 256>>>(pool, p_UV);
    // 10) b_assembled = alpha @ bias(pool cols 4096:4352) + b_base
    gemm64<<<dim3(4, 4, 1), 256>>>(p_al, NPOOL, 0, pool + 4096, DPOOL, 0,
                                   p_bt, DB, 0, BATCH, DB, NPOOL, b_base, 0);
    // 11) W_assembled = alpha @ UV + W_base  (the big one: 68.7 GFLOP)
    wgemm<<<dim3(512, 2, 1), 256>>>(p_al, p_UV, W_base, out_W);
    // 12) h_t = einsum('ba,bca->bc', hA, W_assembled)
    ht_kernel<<<BATCH, 256>>>(out_W, p_hA, p_ht);
    // 13) y + LayerNorm -> hmid
    ln_kernel<<<BATCH, 256>>>(p_hA, p_ht, p_bt, gamma, ln_scale, ln_bias, p_hmid);
    // 14) mid1 = gelu(hmid @ B_w0 + B_b0)   (256x1024, K=256)
    gemm64<<<dim3(16, 4, 1), 256>>>(p_hmid, DA, 0, B_w0, HIDW, 0,
                                    p_mid1, HIDW, 0, BATCH, HIDW, DA, B_b0, 1);
    // 15) output = mid1 @ B_w1 + B_b1       (256x512, K=1024)
    gemm64<<<dim3(8, 4, 1), 256>>>(p_mid1, HIDW, 0, B_w1, DMODEL, 0,
                                   out0, DMODEL, 0, BATCH, DMODEL, HIDW, B_b1, 0);
}

// round 15
// speedup vs baseline: 1.8766x; 1.8760x over previous
#include <cuda_runtime.h>
#include <cuda_bf16.h>
#include <math.h>
#include <stdint.h>

// ---------------- problem constants ----------------
#define BATCH 256
#define DMODEL 512
#define HIDW 1024
#define DA 256
#define DB 256
#define NPOOL 2048
#define DPOOL 4608
#define NASP 4
#define DK 64

// output concat layout (floats)
#define OUT0_OFF   ((size_t)0)
#define ALPHA_OFF  ((size_t)131072)
#define W_OFF      ((size_t)655360)
#define KEYS_OFF   ((size_t)17432576)
#define OUT_TOTAL  ((size_t)17956864)

// ---------------- scratch ----------------
__device__ float g_g1[BATCH * HIDW];
__device__ float g_hA[BATCH * DA];
__device__ float g_queries[BATCH * NASP * DK];
__device__ float g_qw[BATCH * NASP * DK];
__device__ float g_kT[NASP * DK * NPOOL];
__device__ float g_scores[BATCH * NPOOL];
__device__ float g_alpha[BATCH * NPOOL];
__device__ float g_bt[BATCH * DB];
__device__ float g_ht[BATCH * DB];
__device__ float g_hmid[BATCH * DA];
__device__ float g_mid1[BATCH * HIDW];
__device__ float g_keys_fb[NPOOL * NASP * DK];
__device__ float g_W_fb[(size_t)BATCH * DB * DA];
// bf16 operands for tensor-core GEMMs
__device__ __align__(128) __nv_bfloat16 g_alH[BATCH * NPOOL];
__device__ __align__(128) __nv_bfloat16 g_alL[BATCH * NPOOL];
__device__ __align__(128) __nv_bfloat16 g_UVtH[(size_t)DB * DA * NPOOL]; // [de][n]
__device__ __align__(128) __nv_bfloat16 g_UVtL[(size_t)DB * DA * NPOOL];
__device__ __align__(128) __nv_bfloat16 g_poolH[(size_t)NPOOL * DPOOL];
__device__ __align__(128) __nv_bfloat16 g_poolL[(size_t)NPOOL * DPOOL];
__device__ __align__(128) __nv_bfloat16 g_WkTH[NASP * DK * DPOOL];       // [aq][d]
__device__ __align__(128) __nv_bfloat16 g_WkTL[NASP * DK * DPOOL];

__device__ __forceinline__ float gelu_tanh(float x) {
    float x3 = x * x * x;
    return 0.5f * x * (1.0f + tanhf(0.7978845608028654f * (x + 0.044715f * x3)));
}

static __device__ __forceinline__ uint32_t s2u(const void* p) {
    uint32_t a;
    asm("{ .reg .u64 t; cvta.to.shared.u64 t, %1; cvt.u32.u64 %0, t; }" : "=r"(a) : "l"(p));
    return a;
}

// ======================= HMMA (mma.sync) GEMM =======================
// C[M,N] = sum_k (Ah+Al)[m][k]*(Bh+Bl)[n][k] (+bias[n]); drop lo*lo term.
// A: M x K bf16 hi/lo (K-major), B: N x K bf16 hi/lo (K-major).
// CTA tile 128x128, BK=32, 256 threads, 8 warps (2M x 4N), warp tile 64x32.
// smem stage (halves): Ah[128][40] | Al | Bh[128][40] | Bl = 20480 halves.

#define STG_H 20480
#define AH_OFF 0
#define AL_OFF 5120
#define BH_OFF 10240
#define BL_OFF 15360

#define CP16(saddr, gptr) \
    asm volatile("cp.async.cg.shared.global [%0], [%1], 16;" :: "r"(saddr), "l"(gptr))
#define CP_COMMIT() asm volatile("cp.async.commit_group;" ::: "memory")
#define CP_WAIT1()  asm volatile("cp.async.wait_group 1;" ::: "memory")
#define CP_WAIT0()  asm volatile("cp.async.wait_group 0;" ::: "memory")

#define LDSM4(r0, r1, r2, r3, addr) \
    asm volatile("ldmatrix.sync.aligned.m8n8.x4.shared.b16 {%0,%1,%2,%3}, [%4];" \
        : "=r"(r0), "=r"(r1), "=r"(r2), "=r"(r3) : "r"(addr))

#define MMA16816(c, a, b0v, b1v) \
    asm volatile("mma.sync.aligned.m16n8k16.row.col.f32.bf16.bf16.f32 " \
        "{%0,%1,%2,%3}, {%4,%5,%6,%7}, {%8,%9}, {%0,%1,%2,%3};" \
        : "+f"((c)[0]), "+f"((c)[1]), "+f"((c)[2]), "+f"((c)[3]) \
        : "r"((a)[0]), "r"((a)[1]), "r"((a)[2]), "r"((a)[3]), "r"(b0v), "r"(b1v))

__global__ void __launch_bounds__(256, 1) gemm_mma(
    const __nv_bfloat16* __restrict__ Ah, const __nv_bfloat16* __restrict__ Al,
    const __nv_bfloat16* __restrict__ Bh, const __nv_bfloat16* __restrict__ Bl,
    const float* __restrict__ bias, float* __restrict__ C,
    int Kdim, long long ldC)
{
    extern __shared__ __nv_bfloat16 sm[];
    const uint32_t sb = s2u(sm);
    const int tid = threadIdx.x, lane = tid & 31, wid = tid >> 5;
    const int n0 = blockIdx.x * 128, m0 = blockIdx.y * 128;
    const int wm = (wid >> 2) * 64, wn = (wid & 3) * 32;
    const int nsteps = Kdim >> 5;

    // stage-load assignment: 128 rows x 64 bytes per operand.
    // thread covers rows (tid>>2) and (tid>>2)+64, 16-byte chunk (tid&3).
    const int lrow = tid >> 2;          // 0..63
    const int lch  = (tid & 3) * 8;     // halves: 0,8,16,24

    float acc[4][4][4];
    #pragma unroll
    for (int i = 0; i < 4; i++)
        #pragma unroll
        for (int j = 0; j < 4; j++)
            #pragma unroll
            for (int v = 0; v < 4; v++) acc[i][j][v] = 0.0f;

    // ---- prologue: stage 0
    {
        #pragma unroll
        for (int hh = 0; hh < 2; hh++) {
            int row = lrow + hh * 64;
            const __nv_bfloat16* ga  = Ah + (size_t)(m0 + row) * Kdim + lch;
            const __nv_bfloat16* gal = Al + (size_t)(m0 + row) * Kdim + lch;
            const __nv_bfloat16* gb  = Bh + (size_t)(n0 + row) * Kdim + lch;
            const __nv_bfloat16* gbl = Bl + (size_t)(n0 + row) * Kdim + lch;
            uint32_t s0 = sb + (uint32_t)(row * 40 + lch) * 2;
            CP16(s0 + AH_OFF * 2, ga);
            CP16(s0 + AL_OFF * 2, gal);
            CP16(s0 + BH_OFF * 2, gb);
            CP16(s0 + BL_OFF * 2, gbl);
        }
        CP_COMMIT();
    }

    // ldmatrix lane addressing (in halves, relative to operand base)
    const int a_row = lane & 15;
    const int a_koff = (lane >> 4) * 8;
    const int b_row = ((lane >> 4) << 3) + (lane & 7);
    const int b_koff = ((lane >> 3) & 1) * 8;

    for (int s = 0; s < nsteps; s++) {
        if (s + 1 < nsteps) {
            int kk = (s + 1) * 32;
            uint32_t base = ((s + 1) & 1) * STG_H;
            #pragma unroll
            for (int hh = 0; hh < 2; hh++) {
                int row = lrow + hh * 64;
                const __nv_bfloat16* ga  = Ah + (size_t)(m0 + row) * Kdim + kk + lch;
                const __nv_bfloat16* gal = Al + (size_t)(m0 + row) * Kdim + kk + lch;
                const __nv_bfloat16* gb  = Bh + (size_t)(n0 + row) * Kdim + kk + lch;
                const __nv_bfloat16* gbl = Bl + (size_t)(n0 + row) * Kdim + kk + lch;
                uint32_t s0 = sb + (base + (uint32_t)(row * 40 + lch)) * 2;
                CP16(s0 + AH_OFF * 2, ga);
                CP16(s0 + AL_OFF * 2, gal);
                CP16(s0 + BH_OFF * 2, gb);
                CP16(s0 + BL_OFF * 2, gbl);
            }
            CP_COMMIT();
            CP_WAIT1();
        } else {
            CP_WAIT0();
        }
        __syncthreads();

        uint32_t base = (s & 1) * STG_H;
        #pragma unroll
        for (int kp = 0; kp < 2; kp++) {
            uint32_t ah[4][4], al[4][4], bh[8], bl[8];
            #pragma unroll
            for (int mt = 0; mt < 4; mt++) {
                uint32_t off = base + (uint32_t)((wm + mt * 16 + a_row) * 40
                                                 + kp * 16 + a_koff);
                LDSM4(ah[mt][0], ah[mt][1], ah[mt][2], ah[mt][3],
                      sb + (off + AH_OFF) * 2);
                LDSM4(al[mt][0], al[mt][1], al[mt][2], al[mt][3],
                      sb + (off + AL_OFF) * 2);
            }
            #pragma unroll
            for (int np = 0; np < 2; np++) {
                uint32_t off = base + (uint32_t)((wn + np * 16 + b_row) * 40
                                                 + kp * 16 + b_koff);
                LDSM4(bh[np * 4 + 0], bh[np * 4 + 1], bh[np * 4 + 2], bh[np * 4 + 3],
                      sb + (off + BH_OFF) * 2);
                LDSM4(bl[np * 4 + 0], bl[np * 4 + 1], bl[np * 4 + 2], bl[np * 4 + 3],
                      sb + (off + BL_OFF) * 2);
            }
            #pragma unroll
            for (int mt = 0; mt < 4; mt++) {
                #pragma unroll
                for (int nt = 0; nt < 4; nt++) {
                    MMA16816(acc[mt][nt], ah[mt], bh[nt * 2], bh[nt * 2 + 1]);
                    MMA16816(acc[mt][nt], ah[mt], bl[nt * 2], bl[nt * 2 + 1]);
                    MMA16816(acc[mt][nt], al[mt], bh[nt * 2], bh[nt * 2 + 1]);
                }
            }
        }
        __syncthreads();
    }

    // ---- epilogue
    const int er = lane >> 2, ec = (lane & 3) * 2;
    #pragma unroll
    for (int mt = 0; mt < 4; mt++) {
        #pragma unroll
        for (int nt = 0; nt < 4; nt++) {
            int r = m0 + wm + mt * 16 + er;
            int c = n0 + wn + nt * 8 + ec;
            float b0 = 0.0f, b1 = 0.0f;
            if (bias) { b0 = bias[c]; b1 = bias[c + 1]; }
            float2 v0 = make_float2(acc[mt][nt][0] + b0, acc[mt][nt][1] + b1);
            float2 v1 = make_float2(acc[mt][nt][2] + b0, acc[mt][nt][3] + b1);
            *(float2*)(C + (size_t)r * (size_t)ldC + c) = v0;
            *(float2*)(C + (size_t)(r + 8) * (size_t)ldC + c) = v1;
        }
    }
}

// ---------------- fp32 -> bf16 hi/lo split (4 elems/thread) ----------------
__global__ void split_kernel(const float* __restrict__ src,
                             __nv_bfloat16* __restrict__ h,
                             __nv_bfloat16* __restrict__ l, int n4)
{
    int i = blockIdx.x * 256 + threadIdx.x;
    if (i >= n4) return;
    float4 v = *(const float4*)(src + (size_t)i * 4);
    float f[4] = {v.x, v.y, v.z, v.w};
    union { unsigned short s[4]; uint2 u; } ph, pl;
    #pragma unroll
    for (int j = 0; j < 4; j++) {
        __nv_bfloat16 hi = __float2bfloat16(f[j]);
        ph.s[j] = __bfloat16_as_ushort(hi);
        pl.s[j] = __bfloat16_as_ushort(__float2bfloat16(f[j] - __bfloat162float(hi)));
    }
    *(uint2*)((unsigned short*)h + (size_t)i * 4) = ph.u;
    *(uint2*)((unsigned short*)l + (size_t)i * 4) = pl.u;
}

// ---------------- W_K[a][d][q] -> WkT[a*64+q][d] hi/lo ----------------------
__global__ void pack_wk(const float* __restrict__ Wk,
                        __nv_bfloat16* __restrict__ h, __nv_bfloat16* __restrict__ l)
{
    int aq = blockIdx.x;
    int a = aq >> 6, q = aq & 63;
    const float* src = Wk + (size_t)a * DPOOL * DK + q;
    for (int d = threadIdx.x; d < DPOOL; d += 256) {
        float v = src[(size_t)d * DK];
        __nv_bfloat16 hi = __float2bfloat16(v);
        h[(size_t)aq * DPOOL + d] = hi;
        l[(size_t)aq * DPOOL + d] = __float2bfloat16(v - __bfloat162float(hi));
    }
}

// ---------------- UVt[(d*256+e)][n] = sum_r U[n,d,r]*V[n,r,e] (bf16 hi/lo) --
__global__ void __launch_bounds__(256) uvt_build(const float* __restrict__ pool,
                                                 __nv_bfloat16* __restrict__ H,
                                                 __nv_bfloat16* __restrict__ L)
{
    extern __shared__ float Vs[];   // [8][64][64]
    int n0 = blockIdx.x * 64, e0 = blockIdx.y * 64;
    int tid = threadIdx.x;
    {
        int nn = tid >> 2, sub = tid & 3;
        const float* prow = pool + (size_t)(n0 + nn) * DPOOL + 2048 + e0 + sub * 16;
        #pragma unroll
        for (int r = 0; r < 8; r++) {
            const float* src = prow + r * 256;
            #pragma unroll
            for (int j = 0; j < 16; j += 4) {
                float4 v = *(const float4*)(src + j);
                Vs[r * 4096 + (sub * 16 + j + 0) * 64 + nn] = v.x;
                Vs[r * 4096 + (sub * 16 + j + 1) * 64 + nn] = v.y;
                Vs[r * 4096 + (sub * 16 + j + 2) * 64 + nn] = v.z;
                Vs[r * 4096 + (sub * 16 + j + 3) * 64 + nn] = v.w;
            }
        }
    }
    __syncthreads();
    int cn = tid & 63, eg = tid >> 6;
    const float* urow = pool + (size_t)(n0 + cn) * DPOOL;
    for (int dc = 0; dc < 256; dc += 8) {
        float u[8][8];
        #pragma unroll
        for (int dd = 0; dd < 8; dd++) {
            float4 a0 = *(const float4*)(urow + (dc + dd) * 8);
            float4 a1 = *(const float4*)(urow + (dc + dd) * 8 + 4);
            u[dd][0] = a0.x; u[dd][1] = a0.y; u[dd][2] = a0.z; u[dd][3] = a0.w;
            u[dd][4] = a1.x; u[dd][5] = a1.y; u[dd][6] = a1.z; u[dd][7] = a1.w;
        }
        #pragma unroll 2
        for (int i = 0; i < 16; i++) {
            int ee = eg * 16 + i;
            float v[8];
            #pragma unroll
            for (int r = 0; r < 8; r++) v[r] = Vs[r * 4096 + ee * 64 + cn];
            #pragma unroll
            for (int dd = 0; dd < 8; dd++) {
                float acc = 0.0f;
                #pragma unroll
                for (int r = 0; r < 8; r++) acc += v[r] * u[dd][r];
                size_t row = ((size_t)(dc + dd) * 256 + e0 + ee) * 2048 + n0 + cn;
                __nv_bfloat16 hi = __float2bfloat16(acc);
                H[row] = hi;
                L[row] = __float2bfloat16(acc - __bfloat162float(hi));
            }
        }
    }
}

// ---------------- generic tiled SGEMM (small ops) ----------------
__global__ void __launch_bounds__(256) gemm64(
    const float* __restrict__ A, int lda, size_t sA,
    const float* __restrict__ Bm, int ldb, size_t sB,
    float* __restrict__ C, int ldc, size_t sC,
    int M, int N, int K,
    const float* __restrict__ bias, int act)
{
    __shared__ float As[8][64];
    __shared__ float Bs[8][64];
    int z = blockIdx.z;
    A += (size_t)z * sA; Bm += (size_t)z * sB; C += (size_t)z * sC;
    int bm = blockIdx.y * 64, bn = blockIdx.x * 64;
    int tid = threadIdx.x;
    int aRow = tid >> 2, aCol = (tid & 3) * 2;
    int bRow = tid >> 5, bCol = (tid & 31) * 2;
    int ty = tid >> 4, tx = tid & 15;
    float acc[4][4] = {};
    for (int k0 = 0; k0 < K; k0 += 8) {
        int gm = bm + aRow;
        #pragma unroll
        for (int i = 0; i < 2; i++) {
            int gk = k0 + aCol + i;
            As[aCol + i][aRow] = (gm < M && gk < K) ? A[(size_t)gm * lda + gk] : 0.0f;
        }
        int gk2 = k0 + bRow;
        #pragma unroll
        for (int j = 0; j < 2; j++) {
            int gn = bn + bCol + j;
            Bs[bRow][bCol + j] = (gk2 < K && gn < N) ? Bm[(size_t)gk2 * ldb + gn] : 0.0f;
        }
        __syncthreads();
        #pragma unroll
        for (int k = 0; k < 8; k++) {
            float ra[4], rb[4];
            #pragma unroll
            for (int i = 0; i < 4; i++) ra[i] = As[k][ty * 4 + i];
            #pragma unroll
            for (int j = 0; j < 4; j++) rb[j] = Bs[k][tx * 4 + j];
            #pragma unroll
            for (int i = 0; i < 4; i++)
                #pragma unroll
                for (int j = 0; j < 4; j++)
                    acc[i][j] += ra[i] * rb[j];
        }
        __syncthreads();
    }
    #pragma unroll
    for (int i = 0; i < 4; i++) {
        int gm = bm + ty * 4 + i;
        if (gm >= M) continue;
        #pragma unroll
        for (int j = 0; j < 4; j++) {
            int gn = bn + tx * 4 + j;
            if (gn >= N) continue;
            float v = acc[i][j];
            if (bias) v += bias[gn];
            if (act == 1) v = gelu_tanh(v);
            C[(size_t)gm * ldc + gn] = v;
        }
    }
}

// ---------------- small elementwise kernels ----------------
__global__ void qnorm_kernel(const float* __restrict__ q,
                             const float* __restrict__ logits,
                             float* __restrict__ qw)
{
    int b = blockIdx.x;
    int wid = threadIdx.x >> 5, lane = threadIdx.x & 31;
    float l[4];
    #pragma unroll
    for (int a = 0; a < 4; a++) l[a] = logits[a];
    float mx = fmaxf(fmaxf(l[0], l[1]), fmaxf(l[2], l[3]));
    float e[4], sum = 0.0f;
    #pragma unroll
    for (int a = 0; a < 4; a++) { e[a] = expf(l[a] - mx); sum += e[a]; }
    float w = e[wid] / sum;
    const float* row = q + (size_t)b * 256 + wid * 64;
    float v0 = row[lane], v1 = row[lane + 32];
    float ss = v0 * v0 + v1 * v1;
    #pragma unroll
    for (int o = 16; o > 0; o >>= 1) ss += __shfl_xor_sync(0xffffffffu, ss, o);
    float scale = w / (sqrtf(ss) + 1e-8f);
    float* orow = qw + (size_t)b * 256 + wid * 64;
    orow[lane] = v0 * scale;
    orow[lane + 32] = v1 * scale;
}

__global__ void knorm_kernel(const float* __restrict__ keys,
                             float* __restrict__ kT)
{
    int n = blockIdx.x;
    int wid = threadIdx.x >> 5, lane = threadIdx.x & 31;
    const float* row = keys + (size_t)n * 256 + wid * 64;
    float v0 = row[lane], v1 = row[lane + 32];
    float ss = v0 * v0 + v1 * v1;
    #pragma unroll
    for (int o = 16; o > 0; o >>= 1) ss += __shfl_xor_sync(0xffffffffu, ss, o);
    float inv = 1.0f / (sqrtf(ss) + 1e-8f);
    kT[(size_t)(wid * 64 + lane) * NPOOL + n]      = v0 * inv;
    kT[(size_t)(wid * 64 + lane + 32) * NPOOL + n] = v1 * inv;
}

__global__ void alpha_kernel(const float* __restrict__ scores,
                             const float* __restrict__ tau_p,
                             float* __restrict__ alpha_s,
                             float* __restrict__ alpha_o)
{
    int b = blockIdx.x, tid = threadIdx.x;
    float tau = tau_p[0];
    float ar[8], s = 0.0f;
    #pragma unroll
    for (int i = 0; i < 8; i++) {
        int n = tid + i * 256;
        float sc = scores[(size_t)b * NPOOL + n];
        float g = 1.0f / (1.0f + expf(-(sc - tau)));
        float a = g * expf(sc);
        ar[i] = a; s += a;
    }
    __shared__ float red[256];
    red[tid] = s; __syncthreads();
    for (int o = 128; o > 0; o >>= 1) { if (tid < o) red[tid] += red[tid + o]; __syncthreads(); }
    float inv = 1.0f / (red[0] + 1e-8f);
    #pragma unroll
    for (int i = 0; i < 8; i++) {
        int n = tid + i * 256;
        float v = ar[i] * inv;
        alpha_s[(size_t)b * NPOOL + n] = v;
        if (alpha_o != alpha_s) alpha_o[(size_t)b * NPOOL + n] = v;
    }
}

__global__ void __launch_bounds__(256) ht_kernel(const float* __restrict__ W,
                                                 const float* __restrict__ hA,
                                                 float* __restrict__ ht)
{
    int b = blockIdx.x;
    int wid = threadIdx.x >> 5, lane = threadIdx.x & 31;
    __shared__ float ha[256];
    ha[threadIdx.x] = hA[(size_t)b * 256 + threadIdx.x];
    __syncthreads();
    for (int c = wid; c < 256; c += 8) {
        const float* wrow = W + (size_t)b * 65536 + (size_t)c * 256;
        float s = 0.0f;
        #pragma unroll
        for (int j = 0; j < 8; j++) { int a = lane + j * 32; s += wrow[a] * ha[a]; }
        #pragma unroll
        for (int o = 16; o > 0; o >>= 1) s += __shfl_xor_sync(0xffffffffu, s, o);
        if (lane == 0) ht[(size_t)b * 256 + c] = s;
    }
}

__global__ void ln_kernel(const float* __restrict__ hA,
                          const float* __restrict__ ht,
                          const float* __restrict__ bt,
                          const float* __restrict__ gamma_p,
                          const float* __restrict__ ln_s,
                          const float* __restrict__ ln_b,
                          float* __restrict__ hmid)
{
    int b = blockIdx.x, c = threadIdx.x;
    float g = gamma_p[0];
    size_t idx = (size_t)b * 256 + c;
    float y = hA[idx] + g * (ht[idx] + bt[idx]);
    __shared__ float red[256];
    red[c] = y; __syncthreads();
    for (int o = 128; o > 0; o >>= 1) { if (c < o) red[c] += red[c + o]; __syncthreads(); }
    float mu = red[0] * (1.0f / 256.0f);
    __syncthreads();
    float d = y - mu;
    red[c] = d * d; __syncthreads();
    for (int o = 128; o > 0; o >>= 1) { if (c < o) red[c] += red[c + o]; __syncthreads(); }
    float var = red[0] * (1.0f / 256.0f);
    hmid[idx] = d * rsqrtf(var + 1e-6f) * ln_s[c] + ln_b[c];
}

// ---------------- launch ----------------
extern "C" void kernel_launch(void* const* d_in, const int* in_sizes, int n_in,
                              void* d_out, int out_size)
{
    (void)in_sizes; (void)n_in;
    const float* x        = (const float*)d_in[0];
    const float* pool     = (const float*)d_in[1];
    const float* A_w0     = (const float*)d_in[2];
    const float* A_b0     = (const float*)d_in[3];
    const float* A_w1     = (const float*)d_in[4];
    const float* A_b1     = (const float*)d_in[5];
    const float* W_Q      = (const float*)d_in[6];
    const float* W_K      = (const float*)d_in[7];
    const float* logits   = (const float*)d_in[8];
    const float* tau      = (const float*)d_in[9];
    const float* W_base   = (const float*)d_in[10];
    const float* b_base   = (const float*)d_in[11];
    const float* gamma    = (const float*)d_in[12];
    const float* ln_scale = (const float*)d_in[13];
    const float* ln_bias  = (const float*)d_in[14];
    const float* B_w0     = (const float*)d_in[15];
    const float* B_b0     = (const float*)d_in[16];
    const float* B_w1     = (const float*)d_in[17];
    const float* B_b1     = (const float*)d_in[18];
    float* out = (float*)d_out;

    float *p_g1, *p_hA, *p_q, *p_qw, *p_kT, *p_sc, *p_al, *p_bt, *p_ht,
          *p_hmid, *p_mid1, *p_keys_fb, *p_W_fb;
    __nv_bfloat16 *p_alH, *p_alL, *p_UVtH, *p_UVtL, *p_poolH, *p_poolL, *p_WkTH, *p_WkTL;
    cudaGetSymbolAddress((void**)&p_g1, g_g1);
    cudaGetSymbolAddress((void**)&p_hA, g_hA);
    cudaGetSymbolAddress((void**)&p_q, g_queries);
    cudaGetSymbolAddress((void**)&p_qw, g_qw);
    cudaGetSymbolAddress((void**)&p_kT, g_kT);
    cudaGetSymbolAddress((void**)&p_sc, g_scores);
    cudaGetSymbolAddress((void**)&p_al, g_alpha);
    cudaGetSymbolAddress((void**)&p_bt, g_bt);
    cudaGetSymbolAddress((void**)&p_ht, g_ht);
    cudaGetSymbolAddress((void**)&p_hmid, g_hmid);
    cudaGetSymbolAddress((void**)&p_mid1, g_mid1);
    cudaGetSymbolAddress((void**)&p_keys_fb, g_keys_fb);
    cudaGetSymbolAddress((void**)&p_W_fb, g_W_fb);
    cudaGetSymbolAddress((void**)&p_alH, g_alH);
    cudaGetSymbolAddress((void**)&p_alL, g_alL);
    cudaGetSymbolAddress((void**)&p_UVtH, g_UVtH);
    cudaGetSymbolAddress((void**)&p_UVtL, g_UVtL);
    cudaGetSymbolAddress((void**)&p_poolH, g_poolH);
    cudaGetSymbolAddress((void**)&p_poolL, g_poolL);
    cudaGetSymbolAddress((void**)&p_WkTH, g_WkTH);
    cudaGetSymbolAddress((void**)&p_WkTL, g_WkTL);

    cudaFuncSetAttribute(gemm_mma, cudaFuncAttributeMaxDynamicSharedMemorySize, 83968);
    cudaFuncSetAttribute(uvt_build, cudaFuncAttributeMaxDynamicSharedMemorySize, 131072);

    bool full = ((size_t)out_size >= OUT_TOTAL);
    float* out0     = out + OUT0_OFF;
    float* out_al   = full ? out + ALPHA_OFF : p_al;
    float* out_W    = full ? out + W_OFF     : p_W_fb;
    float* out_keys = full ? out + KEYS_OFF  : p_keys_fb;

    // bf16 operand prep
    split_kernel<<<(NPOOL * DPOOL / 4 + 255) / 256, 256>>>(pool, p_poolH, p_poolL,
                                                           NPOOL * DPOOL / 4);
    pack_wk<<<256, 256>>>(W_K, p_WkTH, p_WkTL);
    uvt_build<<<dim3(32, 4), 256, 131072>>>(pool, p_UVtH, p_UVtL);

    // keys = pool @ W_K  (HMMA): M=2048, N=256, K=4608
    gemm_mma<<<dim3(2, 16), 256, 81920>>>(p_poolH, p_poolL, p_WkTH, p_WkTL,
                                          nullptr, out_keys, DPOOL, 256);

    // A-MLP + queries (SIMT)
    gemm64<<<dim3(16, 4, 1), 256>>>(x, DMODEL, 0, A_w0, HIDW, 0,
                                    p_g1, HIDW, 0, BATCH, HIDW, DMODEL, A_b0, 1);
    gemm64<<<dim3(4, 4, 1), 256>>>(p_g1, HIDW, 0, A_w1, DA, 0,
                                   p_hA, DA, 0, BATCH, DA, HIDW, A_b1, 0);
    gemm64<<<dim3(1, 4, NASP), 256>>>(p_hA, DA, 0, W_Q, DK, (size_t)DA * DK,
                                      p_q, DA, DK, BATCH, DK, DA, nullptr, 0);

    qnorm_kernel<<<BATCH, 128>>>(p_q, logits, p_qw);
    knorm_kernel<<<NPOOL, 128>>>(out_keys, p_kT);
    gemm64<<<dim3(32, 4, 1), 256>>>(p_qw, DA, 0, p_kT, NPOOL, 0,
                                    p_sc, NPOOL, 0, BATCH, NPOOL, DA, nullptr, 0);
    alpha_kernel<<<BATCH, 256>>>(p_sc, tau, p_al, out_al);
    split_kernel<<<(BATCH * NPOOL / 4 + 255) / 256, 256>>>(p_al, p_alH, p_alL,
                                                           BATCH * NPOOL / 4);

    // b_assembled (SIMT, small)
    gemm64<<<dim3(4, 4, 1), 256>>>(p_al, NPOOL, 0, pool + 4096, DPOOL, 0,
                                   p_bt, DB, 0, BATCH, DB, NPOOL, b_base, 0);

    // W_assembled = alpha @ UV + W_base (HMMA): M=256, N=65536, K=2048
    gemm_mma<<<dim3(512, 2), 256, 81920>>>(p_alH, p_alL, p_UVtH, p_UVtL,
                                           W_base, out_W, NPOOL, 65536);

    ht_kernel<<<BATCH, 256>>>(out_W, p_hA, p_ht);
    ln_kernel<<<BATCH, 256>>>(p_hA, p_ht, p_bt, gamma, ln_scale, ln_bias, p_hmid);
    gemm64<<<dim3(16, 4, 1), 256>>>(p_hmid, DA, 0, B_w0, HIDW, 0,
                                    p_mid1, HIDW, 0, BATCH, HIDW, DA, B_b0, 1);
    gemm64<<<dim3(8, 4, 1), 256>>>(p_mid1, HIDW, 0, B_w1, DMODEL, 0,
                                   out0, DMODEL, 0, BATCH, DMODEL, HIDW, B_b1, 0);
}

// round 16
// speedup vs baseline: 2.0385x; 1.0863x over previous
#include <cuda_runtime.h>
#include <cuda_bf16.h>
#include <math.h>
#include <stdint.h>

// ---------------- problem constants ----------------
#define BATCH 256
#define DMODEL 512
#define HIDW 1024
#define DA 256
#define DB 256
#define NPOOL 2048
#define DPOOL 4608
#define NASP 4
#define DK 64

// output concat layout (floats)
#define OUT0_OFF   ((size_t)0)
#define ALPHA_OFF  ((size_t)131072)
#define W_OFF      ((size_t)655360)
#define KEYS_OFF   ((size_t)17432576)
#define OUT_TOTAL  ((size_t)17956864)

// ---------------- scratch ----------------
__device__ float g_g1[BATCH * HIDW];
__device__ float g_hA[BATCH * DA];
__device__ float g_queries[BATCH * NASP * DK];
__device__ float g_qw[BATCH * NASP * DK];
__device__ float g_kT[NASP * DK * NPOOL];
__device__ float g_scores[BATCH * NPOOL];
__device__ float g_alpha[BATCH * NPOOL];
__device__ float g_bt[BATCH * DB];
__device__ float g_ht[BATCH * DB];
__device__ float g_hmid[BATCH * DA];
__device__ float g_mid1[BATCH * HIDW];
__device__ float g_keys_fb[NPOOL * NASP * DK];
__device__ float g_W_fb[(size_t)BATCH * DB * DA];
__device__ float g_keys_part[4 * NPOOL * NASP * DK];   // split-K partials
// bf16 operands for tensor-core GEMMs
__device__ __align__(128) __nv_bfloat16 g_alH[BATCH * NPOOL];
__device__ __align__(128) __nv_bfloat16 g_alL[BATCH * NPOOL];
__device__ __align__(128) __nv_bfloat16 g_UVtH[(size_t)DB * DA * NPOOL]; // [de][n]
__device__ __align__(128) __nv_bfloat16 g_UVtL[(size_t)DB * DA * NPOOL];
__device__ __align__(128) __nv_bfloat16 g_poolH[(size_t)NPOOL * DPOOL];
__device__ __align__(128) __nv_bfloat16 g_poolL[(size_t)NPOOL * DPOOL];
__device__ __align__(128) __nv_bfloat16 g_WkTH[NASP * DK * DPOOL];       // [aq][d]
__device__ __align__(128) __nv_bfloat16 g_WkTL[NASP * DK * DPOOL];

__device__ __forceinline__ float gelu_tanh(float x) {
    float x3 = x * x * x;
    return 0.5f * x * (1.0f + tanhf(0.7978845608028654f * (x + 0.044715f * x3)));
}

static __device__ __forceinline__ uint32_t s2u(const void* p) {
    uint32_t a;
    asm("{ .reg .u64 t; cvta.to.shared.u64 t, %1; cvt.u32.u64 %0, t; }" : "=r"(a) : "l"(p));
    return a;
}

// ======================= HMMA (mma.sync) GEMM =======================
// C[M,N] = sum_k (Ah+Al)[m][k]*(Bh+Bl)[n][k] (+bias[n]); drop lo*lo term.
// A: M x K bf16 hi/lo (K-major), B: N x K bf16 hi/lo (K-major).
// CTA tile 128x128, BK=32, 256 threads, 8 warps (2M x 4N), warp tile 64x32.
// 3-stage cp.async pipeline, ONE __syncthreads per K-step.
// Split-K: blockIdx.z covers k range [z*klen, (z+1)*klen); C += z*partStride.
// smem stage (halves): Ah[128][40] | Al | Bh[128][40] | Bl = 20480 halves.

#define STG_H 20480
#define AH_OFF 0
#define AL_OFF 5120
#define BH_OFF 10240
#define BL_OFF 15360
#define TCSMEM (3 * STG_H * 2)   // 122880 bytes

#define CP16(saddr, gptr) \
    asm volatile("cp.async.cg.shared.global [%0], [%1], 16;" :: "r"(saddr), "l"(gptr))
#define CP_COMMIT() asm volatile("cp.async.commit_group;" ::: "memory")
#define CP_WAIT1()  asm volatile("cp.async.wait_group 1;" ::: "memory")
#define CP_WAIT0()  asm volatile("cp.async.wait_group 0;" ::: "memory")

#define LDSM4(r0, r1, r2, r3, addr) \
    asm volatile("ldmatrix.sync.aligned.m8n8.x4.shared.b16 {%0,%1,%2,%3}, [%4];" \
        : "=r"(r0), "=r"(r1), "=r"(r2), "=r"(r3) : "r"(addr))

#define MMA16816(c, a, b0v, b1v) \
    asm volatile("mma.sync.aligned.m16n8k16.row.col.f32.bf16.bf16.f32 " \
        "{%0,%1,%2,%3}, {%4,%5,%6,%7}, {%8,%9}, {%0,%1,%2,%3};" \
        : "+f"((c)[0]), "+f"((c)[1]), "+f"((c)[2]), "+f"((c)[3]) \
        : "r"((a)[0]), "r"((a)[1]), "r"((a)[2]), "r"((a)[3]), "r"(b0v), "r"(b1v))

// one stage-load: 128 rows x 32 halves for 4 operands
#define STAGE_LOAD(kk, base) do { \
    _Pragma("unroll") \
    for (int hh = 0; hh < 2; hh++) { \
        int row = lrow + hh * 64; \
        const __nv_bfloat16* ga  = Ah + (size_t)(m0 + row) * Kstride + (kk) + lch; \
        const __nv_bfloat16* gal = Al + (size_t)(m0 + row) * Kstride + (kk) + lch; \
        const __nv_bfloat16* gb  = Bh + (size_t)(n0 + row) * Kstride + (kk) + lch; \
        const __nv_bfloat16* gbl = Bl + (size_t)(n0 + row) * Kstride + (kk) + lch; \
        uint32_t s0 = sb + ((base) + (uint32_t)(row * 40 + lch)) * 2; \
        CP16(s0 + AH_OFF * 2, ga); \
        CP16(s0 + AL_OFF * 2, gal); \
        CP16(s0 + BH_OFF * 2, gb); \
        CP16(s0 + BL_OFF * 2, gbl); \
    } \
    CP_COMMIT(); \
} while (0)

__global__ void __launch_bounds__(256, 1) gemm_mma(
    const __nv_bfloat16* __restrict__ Ah, const __nv_bfloat16* __restrict__ Al,
    const __nv_bfloat16* __restrict__ Bh, const __nv_bfloat16* __restrict__ Bl,
    const float* __restrict__ bias, float* __restrict__ C,
    int Kstride, int klen, long long ldC, long long partStride)
{
    extern __shared__ __nv_bfloat16 sm[];
    const uint32_t sb = s2u(sm);
    const int tid = threadIdx.x, lane = tid & 31, wid = tid >> 5;
    const int n0 = blockIdx.x * 128, m0 = blockIdx.y * 128;
    const int wm = (wid >> 2) * 64, wn = (wid & 3) * 32;
    const int kbase = blockIdx.z * klen;
    const int nsteps = klen >> 5;
    C += (size_t)blockIdx.z * (size_t)partStride;

    const int lrow = tid >> 2;          // 0..63
    const int lch  = (tid & 3) * 8;     // halves: 0,8,16,24

    float acc[4][4][4];
    #pragma unroll
    for (int i = 0; i < 4; i++)
        #pragma unroll
        for (int j = 0; j < 4; j++)
            #pragma unroll
            for (int v = 0; v < 4; v++) acc[i][j][v] = 0.0f;

    // ---- prologue: stages 0, 1
    STAGE_LOAD(kbase, 0u);
    if (nsteps > 1) STAGE_LOAD(kbase + 32, (uint32_t)STG_H);

    // ldmatrix lane addressing (in halves, relative to operand base)
    const int a_row = lane & 15;
    const int a_koff = (lane >> 4) * 8;
    const int b_row = ((lane >> 4) << 3) + (lane & 7);
    const int b_koff = ((lane >> 3) & 1) * 8;

    for (int s = 0; s < nsteps; s++) {
        if (s + 1 < nsteps) { CP_WAIT1(); } else { CP_WAIT0(); }
        __syncthreads();
        if (s + 2 < nsteps) {
            uint32_t nb = (uint32_t)((s + 2) % 3) * STG_H;
            STAGE_LOAD(kbase + (s + 2) * 32, nb);
        }
        uint32_t base = (uint32_t)(s % 3) * STG_H;
        #pragma unroll
        for (int kp = 0; kp < 2; kp++) {
            uint32_t ah[4][4], al[4][4], bh[8], bl[8];
            #pragma unroll
            for (int mt = 0; mt < 4; mt++) {
                uint32_t off = base + (uint32_t)((wm + mt * 16 + a_row) * 40
                                                 + kp * 16 + a_koff);
                LDSM4(ah[mt][0], ah[mt][1], ah[mt][2], ah[mt][3],
                      sb + (off + AH_OFF) * 2);
                LDSM4(al[mt][0], al[mt][1], al[mt][2], al[mt][3],
                      sb + (off + AL_OFF) * 2);
            }
            #pragma unroll
            for (int np = 0; np < 2; np++) {
                uint32_t off = base + (uint32_t)((wn + np * 16 + b_row) * 40
                                                 + kp * 16 + b_koff);
                LDSM4(bh[np * 4 + 0], bh[np * 4 + 1], bh[np * 4 + 2], bh[np * 4 + 3],
                      sb + (off + BH_OFF) * 2);
                LDSM4(bl[np * 4 + 0], bl[np * 4 + 1], bl[np * 4 + 2], bl[np * 4 + 3],
                      sb + (off + BL_OFF) * 2);
            }
            #pragma unroll
            for (int mt = 0; mt < 4; mt++) {
                #pragma unroll
                for (int nt = 0; nt < 4; nt++) {
                    MMA16816(acc[mt][nt], ah[mt], bh[nt * 2], bh[nt * 2 + 1]);
                    MMA16816(acc[mt][nt], ah[mt], bl[nt * 2], bl[nt * 2 + 1]);
                    MMA16816(acc[mt][nt], al[mt], bh[nt * 2], bh[nt * 2 + 1]);
                }
            }
        }
    }

    // ---- epilogue
    const int er = lane >> 2, ec = (lane & 3) * 2;
    #pragma unroll
    for (int mt = 0; mt < 4; mt++) {
        #pragma unroll
        for (int nt = 0; nt < 4; nt++) {
            int r = m0 + wm + mt * 16 + er;
            int c = n0 + wn + nt * 8 + ec;
            float b0 = 0.0f, b1 = 0.0f;
            if (bias) { b0 = bias[c]; b1 = bias[c + 1]; }
            float2 v0 = make_float2(acc[mt][nt][0] + b0, acc[mt][nt][1] + b1);
            float2 v1 = make_float2(acc[mt][nt][2] + b0, acc[mt][nt][3] + b1);
            *(float2*)(C + (size_t)r * (size_t)ldC + c) = v0;
            *(float2*)(C + (size_t)(r + 8) * (size_t)ldC + c) = v1;
        }
    }
}

// ---------------- reduce 4 split-K partials ----------------
__global__ void reduce4_kernel(const float* __restrict__ p, float* __restrict__ out,
                               int n4, int stride)
{
    int i = blockIdx.x * 256 + threadIdx.x;
    if (i >= n4) return;
    const float4* p0 = (const float4*)p + i;
    const float4* p1 = (const float4*)(p + stride) + i;
    const float4* p2 = (const float4*)(p + 2 * stride) + i;
    const float4* p3 = (const float4*)(p + 3 * stride) + i;
    float4 a = *p0, b = *p1, c = *p2, d = *p3;
    float4 r;
    r.x = (a.x + b.x) + (c.x + d.x);
    r.y = (a.y + b.y) + (c.y + d.y);
    r.z = (a.z + b.z) + (c.z + d.z);
    r.w = (a.w + b.w) + (c.w + d.w);
    ((float4*)out)[i] = r;
}

// ---------------- fp32 -> bf16 hi/lo split (4 elems/thread) ----------------
__global__ void split_kernel(const float* __restrict__ src,
                             __nv_bfloat16* __restrict__ h,
                             __nv_bfloat16* __restrict__ l, int n4)
{
    int i = blockIdx.x * 256 + threadIdx.x;
    if (i >= n4) return;
    float4 v = *(const float4*)(src + (size_t)i * 4);
    float f[4] = {v.x, v.y, v.z, v.w};
    union { unsigned short s[4]; uint2 u; } ph, pl;
    #pragma unroll
    for (int j = 0; j < 4; j++) {
        __nv_bfloat16 hi = __float2bfloat16(f[j]);
        ph.s[j] = __bfloat16_as_ushort(hi);
        pl.s[j] = __bfloat16_as_ushort(__float2bfloat16(f[j] - __bfloat162float(hi)));
    }
    *(uint2*)((unsigned short*)h + (size_t)i * 4) = ph.u;
    *(uint2*)((unsigned short*)l + (size_t)i * 4) = pl.u;
}

// ---------------- W_K[a][d][q] -> WkT[a*64+q][d] hi/lo ----------------------
__global__ void pack_wk(const float* __restrict__ Wk,
                        __nv_bfloat16* __restrict__ h, __nv_bfloat16* __restrict__ l)
{
    int aq = blockIdx.x;
    int a = aq >> 6, q = aq & 63;
    const float* src = Wk + (size_t)a * DPOOL * DK + q;
    for (int d = threadIdx.x; d < DPOOL; d += 256) {
        float v = src[(size_t)d * DK];
        __nv_bfloat16 hi = __float2bfloat16(v);
        h[(size_t)aq * DPOOL + d] = hi;
        l[(size_t)aq * DPOOL + d] = __float2bfloat16(v - __bfloat162float(hi));
    }
}

// ---------------- UVt[(d*256+e)][n] = sum_r U[n,d,r]*V[n,r,e] (bf16 hi/lo) --
__global__ void __launch_bounds__(256) uvt_build(const float* __restrict__ pool,
                                                 __nv_bfloat16* __restrict__ H,
                                                 __nv_bfloat16* __restrict__ L)
{
    extern __shared__ float Vs[];   // [8][64][64]
    int n0 = blockIdx.x * 64, e0 = blockIdx.y * 64;
    int tid = threadIdx.x;
    {
        int nn = tid >> 2, sub = tid & 3;
        const float* prow = pool + (size_t)(n0 + nn) * DPOOL + 2048 + e0 + sub * 16;
        #pragma unroll
        for (int r = 0; r < 8; r++) {
            const float* src = prow + r * 256;
            #pragma unroll
            for (int j = 0; j < 16; j += 4) {
                float4 v = *(const float4*)(src + j);
                Vs[r * 4096 + (sub * 16 + j + 0) * 64 + nn] = v.x;
                Vs[r * 4096 + (sub * 16 + j + 1) * 64 + nn] = v.y;
                Vs[r * 4096 + (sub * 16 + j + 2) * 64 + nn] = v.z;
                Vs[r * 4096 + (sub * 16 + j + 3) * 64 + nn] = v.w;
            }
        }
    }
    __syncthreads();
    int cn = tid & 63, eg = tid >> 6;
    const float* urow = pool + (size_t)(n0 + cn) * DPOOL;
    for (int dc = 0; dc < 256; dc += 8) {
        float u[8][8];
        #pragma unroll
        for (int dd = 0; dd < 8; dd++) {
            float4 a0 = *(const float4*)(urow + (dc + dd) * 8);
            float4 a1 = *(const float4*)(urow + (dc + dd) * 8 + 4);
            u[dd][0] = a0.x; u[dd][1] = a0.y; u[dd][2] = a0.z; u[dd][3] = a0.w;
            u[dd][4] = a1.x; u[dd][5] = a1.y; u[dd][6] = a1.z; u[dd][7] = a1.w;
        }
        #pragma unroll 2
        for (int i = 0; i < 16; i++) {
            int ee = eg * 16 + i;
            float v[8];
            #pragma unroll
            for (int r = 0; r < 8; r++) v[r] = Vs[r * 4096 + ee * 64 + cn];
            #pragma unroll
            for (int dd = 0; dd < 8; dd++) {
                float acc = 0.0f;
                #pragma unroll
                for (int r = 0; r < 8; r++) acc += v[r] * u[dd][r];
                size_t row = ((size_t)(dc + dd) * 256 + e0 + ee) * 2048 + n0 + cn;
                __nv_bfloat16 hi = __float2bfloat16(acc);
                H[row] = hi;
                L[row] = __float2bfloat16(acc - __bfloat162float(hi));
            }
        }
    }
}

// ---------------- generic tiled SGEMM (small ops) ----------------
__global__ void __launch_bounds__(256) gemm64(
    const float* __restrict__ A, int lda, size_t sA,
    const float* __restrict__ Bm, int ldb, size_t sB,
    float* __restrict__ C, int ldc, size_t sC,
    int M, int N, int K,
    const float* __restrict__ bias, int act)
{
    __shared__ float As[8][64];
    __shared__ float Bs[8][64];
    int z = blockIdx.z;
    A += (size_t)z * sA; Bm += (size_t)z * sB; C += (size_t)z * sC;
    int bm = blockIdx.y * 64, bn = blockIdx.x * 64;
    int tid = threadIdx.x;
    int aRow = tid >> 2, aCol = (tid & 3) * 2;
    int bRow = tid >> 5, bCol = (tid & 31) * 2;
    int ty = tid >> 4, tx = tid & 15;
    float acc[4][4] = {};
    for (int k0 = 0; k0 < K; k0 += 8) {
        int gm = bm + aRow;
        #pragma unroll
        for (int i = 0; i < 2; i++) {
            int gk = k0 + aCol + i;
            As[aCol + i][aRow] = (gm < M && gk < K) ? A[(size_t)gm * lda + gk] : 0.0f;
        }
        int gk2 = k0 + bRow;
        #pragma unroll
        for (int j = 0; j < 2; j++) {
            int gn = bn + bCol + j;
            Bs[bRow][bCol + j] = (gk2 < K && gn < N) ? Bm[(size_t)gk2 * ldb + gn] : 0.0f;
        }
        __syncthreads();
        #pragma unroll
        for (int k = 0; k < 8; k++) {
            float ra[4], rb[4];
            #pragma unroll
            for (int i = 0; i < 4; i++) ra[i] = As[k][ty * 4 + i];
            #pragma unroll
            for (int j = 0; j < 4; j++) rb[j] = Bs[k][tx * 4 + j];
            #pragma unroll
            for (int i = 0; i < 4; i++)
                #pragma unroll
                for (int j = 0; j < 4; j++)
                    acc[i][j] += ra[i] * rb[j];
        }
        __syncthreads();
    }
    #pragma unroll
    for (int i = 0; i < 4; i++) {
        int gm = bm + ty * 4 + i;
        if (gm >= M) continue;
        #pragma unroll
        for (int j = 0; j < 4; j++) {
            int gn = bn + tx * 4 + j;
            if (gn >= N) continue;
            float v = acc[i][j];
            if (bias) v += bias[gn];
            if (act == 1) v = gelu_tanh(v);
            C[(size_t)gm * ldc + gn] = v;
        }
    }
}

// ---------------- small elementwise kernels ----------------
__global__ void qnorm_kernel(const float* __restrict__ q,
                             const float* __restrict__ logits,
                             float* __restrict__ qw)
{
    int b = blockIdx.x;
    int wid = threadIdx.x >> 5, lane = threadIdx.x & 31;
    float l[4];
    #pragma unroll
    for (int a = 0; a < 4; a++) l[a] = logits[a];
    float mx = fmaxf(fmaxf(l[0], l[1]), fmaxf(l[2], l[3]));
    float e[4], sum = 0.0f;
    #pragma unroll
    for (int a = 0; a < 4; a++) { e[a] = expf(l[a] - mx); sum += e[a]; }
    float w = e[wid] / sum;
    const float* row = q + (size_t)b * 256 + wid * 64;
    float v0 = row[lane], v1 = row[lane + 32];
    float ss = v0 * v0 + v1 * v1;
    #pragma unroll
    for (int o = 16; o > 0; o >>= 1) ss += __shfl_xor_sync(0xffffffffu, ss, o);
    float scale = w / (sqrtf(ss) + 1e-8f);
    float* orow = qw + (size_t)b * 256 + wid * 64;
    orow[lane] = v0 * scale;
    orow[lane + 32] = v1 * scale;
}

__global__ void knorm_kernel(const float* __restrict__ keys,
                             float* __restrict__ kT)
{
    int n = blockIdx.x;
    int wid = threadIdx.x >> 5, lane = threadIdx.x & 31;
    const float* row = keys + (size_t)n * 256 + wid * 64;
    float v0 = row[lane], v1 = row[lane + 32];
    float ss = v0 * v0 + v1 * v1;
    #pragma unroll
    for (int o = 16; o > 0; o >>= 1) ss += __shfl_xor_sync(0xffffffffu, ss, o);
    float inv = 1.0f / (sqrtf(ss) + 1e-8f);
    kT[(size_t)(wid * 64 + lane) * NPOOL + n]      = v0 * inv;
    kT[(size_t)(wid * 64 + lane + 32) * NPOOL + n] = v1 * inv;
}

__global__ void alpha_kernel(const float* __restrict__ scores,
                             const float* __restrict__ tau_p,
                             float* __restrict__ alpha_s,
                             float* __restrict__ alpha_o)
{
    int b = blockIdx.x, tid = threadIdx.x;
    float tau = tau_p[0];
    float ar[8], s = 0.0f;
    #pragma unroll
    for (int i = 0; i < 8; i++) {
        int n = tid + i * 256;
        float sc = scores[(size_t)b * NPOOL + n];
        float g = 1.0f / (1.0f + expf(-(sc - tau)));
        float a = g * expf(sc);
        ar[i] = a; s += a;
    }
    __shared__ float red[256];
    red[tid] = s; __syncthreads();
    for (int o = 128; o > 0; o >>= 1) { if (tid < o) red[tid] += red[tid + o]; __syncthreads(); }
    float inv = 1.0f / (red[0] + 1e-8f);
    #pragma unroll
    for (int i = 0; i < 8; i++) {
        int n = tid + i * 256;
        float v = ar[i] * inv;
        alpha_s[(size_t)b * NPOOL + n] = v;
        if (alpha_o != alpha_s) alpha_o[(size_t)b * NPOOL + n] = v;
    }
}

__global__ void __launch_bounds__(256) ht_kernel(const float* __restrict__ W,
                                                 const float* __restrict__ hA,
                                                 float* __restrict__ ht)
{
    int b = blockIdx.x;
    int wid = threadIdx.x >> 5, lane = threadIdx.x & 31;
    __shared__ float ha[256];
    ha[threadIdx.x] = hA[(size_t)b * 256 + threadIdx.x];
    __syncthreads();
    for (int c = wid; c < 256; c += 8) {
        const float* wrow = W + (size_t)b * 65536 + (size_t)c * 256;
        float s = 0.0f;
        #pragma unroll
        for (int j = 0; j < 8; j++) { int a = lane + j * 32; s += wrow[a] * ha[a]; }
        #pragma unroll
        for (int o = 16; o > 0; o >>= 1) s += __shfl_xor_sync(0xffffffffu, s, o);
        if (lane == 0) ht[(size_t)b * 256 + c] = s;
    }
}

__global__ void ln_kernel(const float* __restrict__ hA,
                          const float* __restrict__ ht,
                          const float* __restrict__ bt,
                          const float* __restrict__ gamma_p,
                          const float* __restrict__ ln_s,
                          const float* __restrict__ ln_b,
                          float* __restrict__ hmid)
{
    int b = blockIdx.x, c = threadIdx.x;
    float g = gamma_p[0];
    size_t idx = (size_t)b * 256 + c;
    float y = hA[idx] + g * (ht[idx] + bt[idx]);
    __shared__ float red[256];
    red[c] = y; __syncthreads();
    for (int o = 128; o > 0; o >>= 1) { if (c < o) red[c] += red[c + o]; __syncthreads(); }
    float mu = red[0] * (1.0f / 256.0f);
    __syncthreads();
    float d = y - mu;
    red[c] = d * d; __syncthreads();
    for (int o = 128; o > 0; o >>= 1) { if (c < o) red[c] += red[c + o]; __syncthreads(); }
    float var = red[0] * (1.0f / 256.0f);
    hmid[idx] = d * rsqrtf(var + 1e-6f) * ln_s[c] + ln_b[c];
}

// ---------------- launch ----------------
extern "C" void kernel_launch(void* const* d_in, const int* in_sizes, int n_in,
                              void* d_out, int out_size)
{
    (void)in_sizes; (void)n_in;
    const float* x        = (const float*)d_in[0];
    const float* pool     = (const float*)d_in[1];
    const float* A_w0     = (const float*)d_in[2];
    const float* A_b0     = (const float*)d_in[3];
    const float* A_w1     = (const float*)d_in[4];
    const float* A_b1     = (const float*)d_in[5];
    const float* W_Q      = (const float*)d_in[6];
    const float* W_K      = (const float*)d_in[7];
    const float* logits   = (const float*)d_in[8];
    const float* tau      = (const float*)d_in[9];
    const float* W_base   = (const float*)d_in[10];
    const float* b_base   = (const float*)d_in[11];
    const float* gamma    = (const float*)d_in[12];
    const float* ln_scale = (const float*)d_in[13];
    const float* ln_bias  = (const float*)d_in[14];
    const float* B_w0     = (const float*)d_in[15];
    const float* B_b0     = (const float*)d_in[16];
    const float* B_w1     = (const float*)d_in[17];
    const float* B_b1     = (const float*)d_in[18];
    float* out = (float*)d_out;

    float *p_g1, *p_hA, *p_q, *p_qw, *p_kT, *p_sc, *p_al, *p_bt, *p_ht,
          *p_hmid, *p_mid1, *p_keys_fb, *p_W_fb, *p_kpart;
    __nv_bfloat16 *p_alH, *p_alL, *p_UVtH, *p_UVtL, *p_poolH, *p_poolL, *p_WkTH, *p_WkTL;
    cudaGetSymbolAddress((void**)&p_g1, g_g1);
    cudaGetSymbolAddress((void**)&p_hA, g_hA);
    cudaGetSymbolAddress((void**)&p_q, g_queries);
    cudaGetSymbolAddress((void**)&p_qw, g_qw);
    cudaGetSymbolAddress((void**)&p_kT, g_kT);
    cudaGetSymbolAddress((void**)&p_sc, g_scores);
    cudaGetSymbolAddress((void**)&p_al, g_alpha);
    cudaGetSymbolAddress((void**)&p_bt, g_bt);
    cudaGetSymbolAddress((void**)&p_ht, g_ht);
    cudaGetSymbolAddress((void**)&p_hmid, g_hmid);
    cudaGetSymbolAddress((void**)&p_mid1, g_mid1);
    cudaGetSymbolAddress((void**)&p_keys_fb, g_keys_fb);
    cudaGetSymbolAddress((void**)&p_W_fb, g_W_fb);
    cudaGetSymbolAddress((void**)&p_kpart, g_keys_part);
    cudaGetSymbolAddress((void**)&p_alH, g_alH);
    cudaGetSymbolAddress((void**)&p_alL, g_alL);
    cudaGetSymbolAddress((void**)&p_UVtH, g_UVtH);
    cudaGetSymbolAddress((void**)&p_UVtL, g_UVtL);
    cudaGetSymbolAddress((void**)&p_poolH, g_poolH);
    cudaGetSymbolAddress((void**)&p_poolL, g_poolL);
    cudaGetSymbolAddress((void**)&p_WkTH, g_WkTH);
    cudaGetSymbolAddress((void**)&p_WkTL, g_WkTL);

    cudaFuncSetAttribute(gemm_mma, cudaFuncAttributeMaxDynamicSharedMemorySize, TCSMEM);
    cudaFuncSetAttribute(uvt_build, cudaFuncAttributeMaxDynamicSharedMemorySize, 131072);

    bool full = ((size_t)out_size >= OUT_TOTAL);
    float* out0     = out + OUT0_OFF;
    float* out_al   = full ? out + ALPHA_OFF : p_al;
    float* out_W    = full ? out + W_OFF     : p_W_fb;
    float* out_keys = full ? out + KEYS_OFF  : p_keys_fb;

    // bf16 operand prep
    split_kernel<<<(NPOOL * DPOOL / 4 + 255) / 256, 256>>>(pool, p_poolH, p_poolL,
                                                           NPOOL * DPOOL / 4);
    pack_wk<<<256, 256>>>(W_K, p_WkTH, p_WkTL);
    uvt_build<<<dim3(32, 4), 256, 131072>>>(pool, p_UVtH, p_UVtL);

    // keys = pool @ W_K (HMMA, split-K=4): M=2048, N=256, K=4608
    gemm_mma<<<dim3(2, 16, 4), 256, TCSMEM>>>(p_poolH, p_poolL, p_WkTH, p_WkTL,
                                              nullptr, p_kpart, DPOOL, DPOOL / 4,
                                              256, (long long)NPOOL * 256);
    reduce4_kernel<<<(NPOOL * 256 / 4 + 255) / 256, 256>>>(p_kpart, out_keys,
                                                           NPOOL * 256 / 4, NPOOL * 256);

    // A-MLP + queries (SIMT)
    gemm64<<<dim3(16, 4, 1), 256>>>(x, DMODEL, 0, A_w0, HIDW, 0,
                                    p_g1, HIDW, 0, BATCH, HIDW, DMODEL, A_b0, 1);
    gemm64<<<dim3(4, 4, 1), 256>>>(p_g1, HIDW, 0, A_w1, DA, 0,
                                   p_hA, DA, 0, BATCH, DA, HIDW, A_b1, 0);
    gemm64<<<dim3(1, 4, NASP), 256>>>(p_hA, DA, 0, W_Q, DK, (size_t)DA * DK,
                                      p_q, DA, DK, BATCH, DK, DA, nullptr, 0);

    qnorm_kernel<<<BATCH, 128>>>(p_q, logits, p_qw);
    knorm_kernel<<<NPOOL, 128>>>(out_keys, p_kT);
    gemm64<<<dim3(32, 4, 1), 256>>>(p_qw, DA, 0, p_kT, NPOOL, 0,
                                    p_sc, NPOOL, 0, BATCH, NPOOL, DA, nullptr, 0);
    alpha_kernel<<<BATCH, 256>>>(p_sc, tau, p_al, out_al);
    split_kernel<<<(BATCH * NPOOL / 4 + 255) / 256, 256>>>(p_al, p_alH, p_alL,
                                                           BATCH * NPOOL / 4);

    // b_assembled (SIMT, small)
    gemm64<<<dim3(4, 4, 1), 256>>>(p_al, NPOOL, 0, pool + 4096, DPOOL, 0,
                                   p_bt, DB, 0, BATCH, DB, NPOOL, b_base, 0);

    // W_assembled = alpha @ UV + W_base (HMMA): M=256, N=65536, K=2048
    gemm_mma<<<dim3(512, 2, 1), 256, TCSMEM>>>(p_alH, p_alL, p_UVtH, p_UVtL,
                                               W_base, out_W, NPOOL, NPOOL,
                                               65536, 0);

    ht_kernel<<<BATCH, 256>>>(out_W, p_hA, p_ht);
    ln_kernel<<<BATCH, 256>>>(p_hA, p_ht, p_bt, gamma, ln_scale, ln_bias, p_hmid);
    gemm64<<<dim3(16, 4, 1), 256>>>(p_hmid, DA, 0, B_w0, HIDW, 0,
                                    p_mid1, HIDW, 0, BATCH, HIDW, DA, B_b0, 1);
    gemm64<<<dim3(8, 4, 1), 256>>>(p_mid1, HIDW, 0, B_w1, DMODEL, 0,
                                   out0, DMODEL, 0, BATCH, DMODEL, HIDW, B_b1, 0);
}

// round 17
// speedup vs baseline: 2.7480x; 1.3481x over previous
#include <cuda_runtime.h>
#include <cuda_bf16.h>
#include <math.h>
#include <stdint.h>

// ---------------- problem constants ----------------
#define BATCH 256
#define DMODEL 512
#define HIDW 1024
#define DA 256
#define DB 256
#define NPOOL 2048
#define DPOOL 4608
#define NASP 4
#define DK 64

// output concat layout (floats)
#define OUT0_OFF   ((size_t)0)
#define ALPHA_OFF  ((size_t)131072)
#define W_OFF      ((size_t)655360)
#define KEYS_OFF   ((size_t)17432576)
#define OUT_TOTAL  ((size_t)17956864)

// ---------------- scratch ----------------
__device__ float g_queries[BATCH * NASP * DK];
__device__ float g_qw[BATCH * NASP * DK];
__device__ float g_scores[BATCH * NPOOL];
__device__ float g_alpha[BATCH * NPOOL];
__device__ float g_g1[BATCH * HIDW];
__device__ float g_hA[BATCH * DA];
__device__ float g_bt[BATCH * DB];
__device__ float g_ht[BATCH * DB];
__device__ float g_hmid[BATCH * DA];
__device__ float g_mid1[BATCH * HIDW];
__device__ float g_keys_fb[NPOOL * NASP * DK];
__device__ float g_W_fb[(size_t)BATCH * DB * DA];
__device__ float g_keys_part[4 * NPOOL * NASP * DK];   // split-K partials
// bf16 hi/lo operands
__device__ __align__(128) __nv_bfloat16 g_alH[BATCH * NPOOL];
__device__ __align__(128) __nv_bfloat16 g_alL[BATCH * NPOOL];
__device__ __align__(128) __nv_bfloat16 g_UVtH[(size_t)DB * DA * NPOOL]; // [de][n]
__device__ __align__(128) __nv_bfloat16 g_UVtL[(size_t)DB * DA * NPOOL];
__device__ __align__(128) __nv_bfloat16 g_poolH[(size_t)NPOOL * DPOOL];
__device__ __align__(128) __nv_bfloat16 g_poolL[(size_t)NPOOL * DPOOL];
__device__ __align__(128) __nv_bfloat16 g_WkTH[NASP * DK * DPOOL];       // [aq][d]
__device__ __align__(128) __nv_bfloat16 g_WkTL[NASP * DK * DPOOL];
// activation splits
__device__ __align__(128) __nv_bfloat16 g_xH[BATCH * DMODEL];
__device__ __align__(128) __nv_bfloat16 g_xL[BATCH * DMODEL];
__device__ __align__(128) __nv_bfloat16 g_g1H[BATCH * HIDW];
__device__ __align__(128) __nv_bfloat16 g_g1L[BATCH * HIDW];
__device__ __align__(128) __nv_bfloat16 g_hAH[BATCH * DA];
__device__ __align__(128) __nv_bfloat16 g_hAL[BATCH * DA];
__device__ __align__(128) __nv_bfloat16 g_qwH[BATCH * DA];
__device__ __align__(128) __nv_bfloat16 g_qwL[BATCH * DA];
__device__ __align__(128) __nv_bfloat16 g_hmH[BATCH * DA];
__device__ __align__(128) __nv_bfloat16 g_hmL[BATCH * DA];
__device__ __align__(128) __nv_bfloat16 g_m1H[BATCH * HIDW];
__device__ __align__(128) __nv_bfloat16 g_m1L[BATCH * HIDW];
__device__ __align__(128) __nv_bfloat16 g_kH[NPOOL * DA];   // k_norm [n][aq]
__device__ __align__(128) __nv_bfloat16 g_kL[NPOOL * DA];
// weight packs (transposed, K-major)
__device__ __align__(128) __nv_bfloat16 g_w0TH[HIDW * DMODEL];
__device__ __align__(128) __nv_bfloat16 g_w0TL[HIDW * DMODEL];
__device__ __align__(128) __nv_bfloat16 g_w1TH[DA * HIDW];
__device__ __align__(128) __nv_bfloat16 g_w1TL[DA * HIDW];
__device__ __align__(128) __nv_bfloat16 g_bw0TH[HIDW * DA];
__device__ __align__(128) __nv_bfloat16 g_bw0TL[HIDW * DA];
__device__ __align__(128) __nv_bfloat16 g_bw1TH[DMODEL * HIDW];
__device__ __align__(128) __nv_bfloat16 g_bw1TL[DMODEL * HIDW];
__device__ __align__(128) __nv_bfloat16 g_wqTH[DA * DA];
__device__ __align__(128) __nv_bfloat16 g_wqTL[DA * DA];
__device__ __align__(128) __nv_bfloat16 g_biasTH[DB * NPOOL];
__device__ __align__(128) __nv_bfloat16 g_biasTL[DB * NPOOL];

__device__ __forceinline__ float gelu_tanh(float x) {
    float x3 = x * x * x;
    return 0.5f * x * (1.0f + tanhf(0.7978845608028654f * (x + 0.044715f * x3)));
}

static __device__ __forceinline__ uint32_t s2u(const void* p) {
    uint32_t a;
    asm("{ .reg .u64 t; cvta.to.shared.u64 t, %1; cvt.u32.u64 %0, t; }" : "=r"(a) : "l"(p));
    return a;
}

// ======================= HMMA (mma.sync) GEMM =======================
// C[M,N] = act(sum_k (Ah+Al)[m][k]*(Bh+Bl)[n][k] + bias[n]); drop lo*lo.
// CTA tile 128x128, BK=32, 256 threads, 8 warps (2Mx4N), warp tile 64x32.
// 2-stage cp.async pipeline, ONE __syncthreads per step, 2 CTAs/SM.
// smem stage (halves): Ah[128][40] | Al | Bh[128][40] | Bl = 20480 halves.

#define STG_H 20480
#define AH_OFF 0
#define AL_OFF 5120
#define BH_OFF 10240
#define BL_OFF 15360
#define TCSMEM (2 * STG_H * 2)   // 81920 bytes

#define CP16(saddr, gptr) \
    asm volatile("cp.async.cg.shared.global [%0], [%1], 16;" :: "r"(saddr), "l"(gptr))
#define CP_COMMIT() asm volatile("cp.async.commit_group;" ::: "memory")
#define CP_WAIT0()  asm volatile("cp.async.wait_group 0;" ::: "memory")

#define LDSM4(r0, r1, r2, r3, addr) \
    asm volatile("ldmatrix.sync.aligned.m8n8.x4.shared.b16 {%0,%1,%2,%3}, [%4];" \
        : "=r"(r0), "=r"(r1), "=r"(r2), "=r"(r3) : "r"(addr))

#define MMA16816(c, a, b0v, b1v) \
    asm volatile("mma.sync.aligned.m16n8k16.row.col.f32.bf16.bf16.f32 " \
        "{%0,%1,%2,%3}, {%4,%5,%6,%7}, {%8,%9}, {%0,%1,%2,%3};" \
        : "+f"((c)[0]), "+f"((c)[1]), "+f"((c)[2]), "+f"((c)[3]) \
        : "r"((a)[0]), "r"((a)[1]), "r"((a)[2]), "r"((a)[3]), "r"(b0v), "r"(b1v))

#define STAGE_LOAD(kk, base) do { \
    _Pragma("unroll") \
    for (int hh = 0; hh < 2; hh++) { \
        int row = lrow + hh * 64; \
        const __nv_bfloat16* ga  = Ah + (size_t)(m0 + row) * Kstride + (kk) + lch; \
        const __nv_bfloat16* gal = Al + (size_t)(m0 + row) * Kstride + (kk) + lch; \
        const __nv_bfloat16* gb  = Bh + (size_t)(n0 + row) * Kstride + (kk) + lch; \
        const __nv_bfloat16* gbl = Bl + (size_t)(n0 + row) * Kstride + (kk) + lch; \
        uint32_t s0 = sb + ((base) + (uint32_t)(row * 40 + lch)) * 2; \
        CP16(s0 + AH_OFF * 2, ga); \
        CP16(s0 + AL_OFF * 2, gal); \
        CP16(s0 + BH_OFF * 2, gb); \
        CP16(s0 + BL_OFF * 2, gbl); \
    } \
    CP_COMMIT(); \
} while (0)

__global__ void __launch_bounds__(256, 2) gemm_mma(
    const __nv_bfloat16* __restrict__ Ah, const __nv_bfloat16* __restrict__ Al,
    const __nv_bfloat16* __restrict__ Bh, const __nv_bfloat16* __restrict__ Bl,
    const float* __restrict__ bias, float* __restrict__ C,
    int Kstride, int klen, long long ldC, long long partStride, int act)
{
    extern __shared__ __nv_bfloat16 sm[];
    const uint32_t sb = s2u(sm);
    const int tid = threadIdx.x, lane = tid & 31, wid = tid >> 5;
    const int n0 = blockIdx.x * 128, m0 = blockIdx.y * 128;
    const int wm = (wid >> 2) * 64, wn = (wid & 3) * 32;
    const int kbase = blockIdx.z * klen;
    const int nsteps = klen >> 5;
    C += (size_t)blockIdx.z * (size_t)partStride;

    const int lrow = tid >> 2;          // 0..63
    const int lch  = (tid & 3) * 8;     // halves: 0,8,16,24

    float acc[4][4][4];
    #pragma unroll
    for (int i = 0; i < 4; i++)
        #pragma unroll
        for (int j = 0; j < 4; j++)
            #pragma unroll
            for (int v = 0; v < 4; v++) acc[i][j][v] = 0.0f;

    STAGE_LOAD(kbase, 0u);

    const int a_row = lane & 15;
    const int a_koff = (lane >> 4) * 8;
    const int b_row = ((lane >> 4) << 3) + (lane & 7);
    const int b_koff = ((lane >> 3) & 1) * 8;

    for (int s = 0; s < nsteps; s++) {
        CP_WAIT0();
        __syncthreads();
        if (s + 1 < nsteps) {
            // safe: sync above proves all warps finished reading this buffer
            STAGE_LOAD(kbase + (s + 1) * 32, (uint32_t)((s + 1) & 1) * STG_H);
        }
        uint32_t base = (uint32_t)(s & 1) * STG_H;
        #pragma unroll
        for (int kp = 0; kp < 2; kp++) {
            uint32_t ah[4][4], al[4][4], bh[8], bl[8];
            #pragma unroll
            for (int mt = 0; mt < 4; mt++) {
                uint32_t off = base + (uint32_t)((wm + mt * 16 + a_row) * 40
                                                 + kp * 16 + a_koff);
                LDSM4(ah[mt][0], ah[mt][1], ah[mt][2], ah[mt][3],
                      sb + (off + AH_OFF) * 2);
                LDSM4(al[mt][0], al[mt][1], al[mt][2], al[mt][3],
                      sb + (off + AL_OFF) * 2);
            }
            #pragma unroll
            for (int np = 0; np < 2; np++) {
                uint32_t off = base + (uint32_t)((wn + np * 16 + b_row) * 40
                                                 + kp * 16 + b_koff);
                LDSM4(bh[np * 4 + 0], bh[np * 4 + 1], bh[np * 4 + 2], bh[np * 4 + 3],
                      sb + (off + BH_OFF) * 2);
                LDSM4(bl[np * 4 + 0], bl[np * 4 + 1], bl[np * 4 + 2], bl[np * 4 + 3],
                      sb + (off + BL_OFF) * 2);
            }
            #pragma unroll
            for (int mt = 0; mt < 4; mt++) {
                #pragma unroll
                for (int nt = 0; nt < 4; nt++) {
                    MMA16816(acc[mt][nt], ah[mt], bh[nt * 2], bh[nt * 2 + 1]);
                    MMA16816(acc[mt][nt], ah[mt], bl[nt * 2], bl[nt * 2 + 1]);
                    MMA16816(acc[mt][nt], al[mt], bh[nt * 2], bh[nt * 2 + 1]);
                }
            }
        }
    }

    // ---- epilogue
    const int er = lane >> 2, ec = (lane & 3) * 2;
    #pragma unroll
    for (int mt = 0; mt < 4; mt++) {
        #pragma unroll
        for (int nt = 0; nt < 4; nt++) {
            int r = m0 + wm + mt * 16 + er;
            int c = n0 + wn + nt * 8 + ec;
            float b0 = 0.0f, b1 = 0.0f;
            if (bias) { b0 = bias[c]; b1 = bias[c + 1]; }
            float v00 = acc[mt][nt][0] + b0, v01 = acc[mt][nt][1] + b1;
            float v10 = acc[mt][nt][2] + b0, v11 = acc[mt][nt][3] + b1;
            if (act) {
                v00 = gelu_tanh(v00); v01 = gelu_tanh(v01);
                v10 = gelu_tanh(v10); v11 = gelu_tanh(v11);
            }
            *(float2*)(C + (size_t)r * (size_t)ldC + c) = make_float2(v00, v01);
            *(float2*)(C + (size_t)(r + 8) * (size_t)ldC + c) = make_float2(v10, v11);
        }
    }
}

// ---------------- reduce 4 split-K partials ----------------
__global__ void reduce4_kernel(const float* __restrict__ p, float* __restrict__ out,
                               int n4, int stride)
{
    int i = blockIdx.x * 256 + threadIdx.x;
    if (i >= n4) return;
    float4 a = ((const float4*)p)[i];
    float4 b = ((const float4*)(p + stride))[i];
    float4 c = ((const float4*)(p + 2 * stride))[i];
    float4 d = ((const float4*)(p + 3 * stride))[i];
    float4 r;
    r.x = (a.x + b.x) + (c.x + d.x);
    r.y = (a.y + b.y) + (c.y + d.y);
    r.z = (a.z + b.z) + (c.z + d.z);
    r.w = (a.w + b.w) + (c.w + d.w);
    ((float4*)out)[i] = r;
}

// ---------------- fp32 -> bf16 hi/lo split (contiguous) ----------------
__global__ void split_kernel(const float* __restrict__ src,
                             __nv_bfloat16* __restrict__ h,
                             __nv_bfloat16* __restrict__ l, int n4)
{
    int i = blockIdx.x * 256 + threadIdx.x;
    if (i >= n4) return;
    float4 v = *(const float4*)(src + (size_t)i * 4);
    float f[4] = {v.x, v.y, v.z, v.w};
    union { unsigned short s[4]; uint2 u; } ph, pl;
    #pragma unroll
    for (int j = 0; j < 4; j++) {
        __nv_bfloat16 hi = __float2bfloat16(f[j]);
        ph.s[j] = __bfloat16_as_ushort(hi);
        pl.s[j] = __bfloat16_as_ushort(__float2bfloat16(f[j] - __bfloat162float(hi)));
    }
    *(uint2*)((unsigned short*)h + (size_t)i * 4) = ph.u;
    *(uint2*)((unsigned short*)l + (size_t)i * 4) = pl.u;
}

// ---------------- transpose + split: out[c][r] = split(src[r*lda+c]) --------
__global__ void tsplit(const float* __restrict__ src, int lda, int R, int C,
                       __nv_bfloat16* __restrict__ H, __nv_bfloat16* __restrict__ L,
                       int ldo)
{
    __shared__ float t[32][33];
    int c0 = blockIdx.x * 32, r0 = blockIdx.y * 32;
    for (int i = threadIdx.y; i < 32; i += 8) {
        int r = r0 + i, c = c0 + threadIdx.x;
        t[i][threadIdx.x] = (r < R && c < C) ? src[(size_t)r * lda + c] : 0.0f;
    }
    __syncthreads();
    for (int i = threadIdx.y; i < 32; i += 8) {
        int c = c0 + i, r = r0 + threadIdx.x;
        if (c < C && r < R) {
            float v = t[threadIdx.x][i];
            __nv_bfloat16 hi = __float2bfloat16(v);
            H[(size_t)c * ldo + r] = hi;
            L[(size_t)c * ldo + r] = __float2bfloat16(v - __bfloat162float(hi));
        }
    }
}

// ---------------- W_K[a][d][q] -> WkT[a*64+q][d] hi/lo ----------------------
__global__ void pack_wk(const float* __restrict__ Wk,
                        __nv_bfloat16* __restrict__ h, __nv_bfloat16* __restrict__ l)
{
    int aq = blockIdx.x;
    int a = aq >> 6, q = aq & 63;
    const float* src = Wk + (size_t)a * DPOOL * DK + q;
    for (int d = threadIdx.x; d < DPOOL; d += 256) {
        float v = src[(size_t)d * DK];
        __nv_bfloat16 hi = __float2bfloat16(v);
        h[(size_t)aq * DPOOL + d] = hi;
        l[(size_t)aq * DPOOL + d] = __float2bfloat16(v - __bfloat162float(hi));
    }
}

// ---------------- UVt[(d*256+e)][n] = sum_r U[n,d,r]*V[n,r,e] (bf16 hi/lo) --
__global__ void __launch_bounds__(256) uvt_build(const float* __restrict__ pool,
                                                 __nv_bfloat16* __restrict__ H,
                                                 __nv_bfloat16* __restrict__ L)
{
    extern __shared__ float Vs[];   // [8][64][64]
    int n0 = blockIdx.x * 64, e0 = blockIdx.y * 64;
    int tid = threadIdx.x;
    {
        int nn = tid >> 2, sub = tid & 3;
        const float* prow = pool + (size_t)(n0 + nn) * DPOOL + 2048 + e0 + sub * 16;
        #pragma unroll
        for (int r = 0; r < 8; r++) {
            const float* src = prow + r * 256;
            #pragma unroll
            for (int j = 0; j < 16; j += 4) {
                float4 v = *(const float4*)(src + j);
                Vs[r * 4096 + (sub * 16 + j + 0) * 64 + nn] = v.x;
                Vs[r * 4096 + (sub * 16 + j + 1) * 64 + nn] = v.y;
                Vs[r * 4096 + (sub * 16 + j + 2) * 64 + nn] = v.z;
                Vs[r * 4096 + (sub * 16 + j + 3) * 64 + nn] = v.w;
            }
        }
    }
    __syncthreads();
    int cn = tid & 63, eg = tid >> 6;
    const float* urow = pool + (size_t)(n0 + cn) * DPOOL;
    for (int dc = 0; dc < 256; dc += 8) {
        float u[8][8];
        #pragma unroll
        for (int dd = 0; dd < 8; dd++) {
            float4 a0 = *(const float4*)(urow + (dc + dd) * 8);
            float4 a1 = *(const float4*)(urow + (dc + dd) * 8 + 4);
            u[dd][0] = a0.x; u[dd][1] = a0.y; u[dd][2] = a0.z; u[dd][3] = a0.w;
            u[dd][4] = a1.x; u[dd][5] = a1.y; u[dd][6] = a1.z; u[dd][7] = a1.w;
        }
        #pragma unroll 2
        for (int i = 0; i < 16; i++) {
            int ee = eg * 16 + i;
            float v[8];
            #pragma unroll
            for (int r = 0; r < 8; r++) v[r] = Vs[r * 4096 + ee * 64 + cn];
            #pragma unroll
            for (int dd = 0; dd < 8; dd++) {
                float acc = 0.0f;
                #pragma unroll
                for (int r = 0; r < 8; r++) acc += v[r] * u[dd][r];
                size_t row = ((size_t)(dc + dd) * 256 + e0 + ee) * 2048 + n0 + cn;
                __nv_bfloat16 hi = __float2bfloat16(acc);
                H[row] = hi;
                L[row] = __float2bfloat16(acc - __bfloat162float(hi));
            }
        }
    }
}

// ---------------- small elementwise kernels ----------------
__global__ void qnorm_kernel(const float* __restrict__ q,
                             const float* __restrict__ logits,
                             float* __restrict__ qw)
{
    int b = blockIdx.x;
    int wid = threadIdx.x >> 5, lane = threadIdx.x & 31;
    float l[4];
    #pragma unroll
    for (int a = 0; a < 4; a++) l[a] = logits[a];
    float mx = fmaxf(fmaxf(l[0], l[1]), fmaxf(l[2], l[3]));
    float e[4], sum = 0.0f;
    #pragma unroll
    for (int a = 0; a < 4; a++) { e[a] = expf(l[a] - mx); sum += e[a]; }
    float w = e[wid] / sum;
    const float* row = q + (size_t)b * 256 + wid * 64;
    float v0 = row[lane], v1 = row[lane + 32];
    float ss = v0 * v0 + v1 * v1;
    #pragma unroll
    for (int o = 16; o > 0; o >>= 1) ss += __shfl_xor_sync(0xffffffffu, ss, o);
    float scale = w / (sqrtf(ss) + 1e-8f);
    float* orow = qw + (size_t)b * 256 + wid * 64;
    orow[lane] = v0 * scale;
    orow[lane + 32] = v1 * scale;
}

// k normalization -> bf16 hi/lo [n][256] (B operand for scores GEMM)
__global__ void knorm_kernel(const float* __restrict__ keys,
                             __nv_bfloat16* __restrict__ kH,
                             __nv_bfloat16* __restrict__ kL)
{
    int n = blockIdx.x;
    int wid = threadIdx.x >> 5, lane = threadIdx.x & 31;
    const float* row = keys + (size_t)n * 256 + wid * 64;
    float v0 = row[lane], v1 = row[lane + 32];
    float ss = v0 * v0 + v1 * v1;
    #pragma unroll
    for (int o = 16; o > 0; o >>= 1) ss += __shfl_xor_sync(0xffffffffu, ss, o);
    float inv = 1.0f / (sqrtf(ss) + 1e-8f);
    float a0 = v0 * inv, a1 = v1 * inv;
    size_t i0 = (size_t)n * 256 + wid * 64 + lane;
    __nv_bfloat16 h0 = __float2bfloat16(a0);
    __nv_bfloat16 h1 = __float2bfloat16(a1);
    kH[i0] = h0;      kL[i0] = __float2bfloat16(a0 - __bfloat162float(h0));
    kH[i0 + 32] = h1; kL[i0 + 32] = __float2bfloat16(a1 - __bfloat162float(h1));
}

__global__ void alpha_kernel(const float* __restrict__ scores,
                             const float* __restrict__ tau_p,
                             float* __restrict__ alpha_s,
                             float* __restrict__ alpha_o)
{
    int b = blockIdx.x, tid = threadIdx.x;
    float tau = tau_p[0];
    float ar[8], s = 0.0f;
    #pragma unroll
    for (int i = 0; i < 8; i++) {
        int n = tid + i * 256;
        float sc = scores[(size_t)b * NPOOL + n];
        float g = 1.0f / (1.0f + expf(-(sc - tau)));
        float a = g * expf(sc);
        ar[i] = a; s += a;
    }
    __shared__ float red[256];
    red[tid] = s; __syncthreads();
    for (int o = 128; o > 0; o >>= 1) { if (tid < o) red[tid] += red[tid + o]; __syncthreads(); }
    float inv = 1.0f / (red[0] + 1e-8f);
    #pragma unroll
    for (int i = 0; i < 8; i++) {
        int n = tid + i * 256;
        float v = ar[i] * inv;
        alpha_s[(size_t)b * NPOOL + n] = v;
        if (alpha_o != alpha_s) alpha_o[(size_t)b * NPOOL + n] = v;
    }
}

__global__ void __launch_bounds__(256) ht_kernel(const float* __restrict__ W,
                                                 const float* __restrict__ hA,
                                                 float* __restrict__ ht)
{
    int b = blockIdx.x;
    int wid = threadIdx.x >> 5, lane = threadIdx.x & 31;
    __shared__ float ha[256];
    ha[threadIdx.x] = hA[(size_t)b * 256 + threadIdx.x];
    __syncthreads();
    for (int c = wid; c < 256; c += 8) {
        const float* wrow = W + (size_t)b * 65536 + (size_t)c * 256;
        float s = 0.0f;
        #pragma unroll
        for (int j = 0; j < 8; j++) { int a = lane + j * 32; s += wrow[a] * ha[a]; }
        #pragma unroll
        for (int o = 16; o > 0; o >>= 1) s += __shfl_xor_sync(0xffffffffu, s, o);
        if (lane == 0) ht[(size_t)b * 256 + c] = s;
    }
}

__global__ void ln_kernel(const float* __restrict__ hA,
                          const float* __restrict__ ht,
                          const float* __restrict__ bt,
                          const float* __restrict__ gamma_p,
                          const float* __restrict__ ln_s,
                          const float* __restrict__ ln_b,
                          float* __restrict__ hmid)
{
    int b = blockIdx.x, c = threadIdx.x;
    float g = gamma_p[0];
    size_t idx = (size_t)b * 256 + c;
    float y = hA[idx] + g * (ht[idx] + bt[idx]);
    __shared__ float red[256];
    red[c] = y; __syncthreads();
    for (int o = 128; o > 0; o >>= 1) { if (c < o) red[c] += red[c + o]; __syncthreads(); }
    float mu = red[0] * (1.0f / 256.0f);
    __syncthreads();
    float d = y - mu;
    red[c] = d * d; __syncthreads();
    for (int o = 128; o > 0; o >>= 1) { if (c < o) red[c] += red[c + o]; __syncthreads(); }
    float var = red[0] * (1.0f / 256.0f);
    hmid[idx] = d * rsqrtf(var + 1e-6f) * ln_s[c] + ln_b[c];
}

// ---------------- launch ----------------
extern "C" void kernel_launch(void* const* d_in, const int* in_sizes, int n_in,
                              void* d_out, int out_size)
{
    (void)in_sizes; (void)n_in;
    const float* x        = (const float*)d_in[0];
    const float* pool     = (const float*)d_in[1];
    const float* A_w0     = (const float*)d_in[2];
    const float* A_b0     = (const float*)d_in[3];
    const float* A_w1     = (const float*)d_in[4];
    const float* A_b1     = (const float*)d_in[5];
    const float* W_Q      = (const float*)d_in[6];
    const float* W_K      = (const float*)d_in[7];
    const float* logits   = (const float*)d_in[8];
    const float* tau      = (const float*)d_in[9];
    const float* W_base   = (const float*)d_in[10];
    const float* b_base   = (const float*)d_in[11];
    const float* gamma    = (const float*)d_in[12];
    const float* ln_scale = (const float*)d_in[13];
    const float* ln_bias  = (const float*)d_in[14];
    const float* B_w0     = (const float*)d_in[15];
    const float* B_b0     = (const float*)d_in[16];
    const float* B_w1     = (const float*)d_in[17];
    const float* B_b1     = (const float*)d_in[18];
    float* out = (float*)d_out;

    float *p_q, *p_qw, *p_sc, *p_al, *p_g1, *p_hA, *p_bt, *p_ht, *p_hmid, *p_mid1,
          *p_keys_fb, *p_W_fb, *p_kpart;
    cudaGetSymbolAddress((void**)&p_q, g_queries);
    cudaGetSymbolAddress((void**)&p_qw, g_qw);
    cudaGetSymbolAddress((void**)&p_sc, g_scores);
    cudaGetSymbolAddress((void**)&p_al, g_alpha);
    cudaGetSymbolAddress((void**)&p_g1, g_g1);
    cudaGetSymbolAddress((void**)&p_hA, g_hA);
    cudaGetSymbolAddress((void**)&p_bt, g_bt);
    cudaGetSymbolAddress((void**)&p_ht, g_ht);
    cudaGetSymbolAddress((void**)&p_hmid, g_hmid);
    cudaGetSymbolAddress((void**)&p_mid1, g_mid1);
    cudaGetSymbolAddress((void**)&p_keys_fb, g_keys_fb);
    cudaGetSymbolAddress((void**)&p_W_fb, g_W_fb);
    cudaGetSymbolAddress((void**)&p_kpart, g_keys_part);

    __nv_bfloat16 *p_alH, *p_alL, *p_UVtH, *p_UVtL, *p_poolH, *p_poolL,
        *p_WkTH, *p_WkTL, *p_xH, *p_xL, *p_g1H, *p_g1L, *p_hAH, *p_hAL,
        *p_qwH, *p_qwL, *p_hmH, *p_hmL, *p_m1H, *p_m1L, *p_kH, *p_kL,
        *p_w0TH, *p_w0TL, *p_w1TH, *p_w1TL, *p_bw0TH, *p_bw0TL,
        *p_bw1TH, *p_bw1TL, *p_wqTH, *p_wqTL, *p_biasTH, *p_biasTL;
    cudaGetSymbolAddress((void**)&p_alH, g_alH);
    cudaGetSymbolAddress((void**)&p_alL, g_alL);
    cudaGetSymbolAddress((void**)&p_UVtH, g_UVtH);
    cudaGetSymbolAddress((void**)&p_UVtL, g_UVtL);
    cudaGetSymbolAddress((void**)&p_poolH, g_poolH);
    cudaGetSymbolAddress((void**)&p_poolL, g_poolL);
    cudaGetSymbolAddress((void**)&p_WkTH, g_WkTH);
    cudaGetSymbolAddress((void**)&p_WkTL, g_WkTL);
    cudaGetSymbolAddress((void**)&p_xH, g_xH);
    cudaGetSymbolAddress((void**)&p_xL, g_xL);
    cudaGetSymbolAddress((void**)&p_g1H, g_g1H);
    cudaGetSymbolAddress((void**)&p_g1L, g_g1L);
    cudaGetSymbolAddress((void**)&p_hAH, g_hAH);
    cudaGetSymbolAddress((void**)&p_hAL, g_hAL);
    cudaGetSymbolAddress((void**)&p_qwH, g_qwH);
    cudaGetSymbolAddress((void**)&p_qwL, g_qwL);
    cudaGetSymbolAddress((void**)&p_hmH, g_hmH);
    cudaGetSymbolAddress((void**)&p_hmL, g_hmL);
    cudaGetSymbolAddress((void**)&p_m1H, g_m1H);
    cudaGetSymbolAddress((void**)&p_m1L, g_m1L);
    cudaGetSymbolAddress((void**)&p_kH, g_kH);
    cudaGetSymbolAddress((void**)&p_kL, g_kL);
    cudaGetSymbolAddress((void**)&p_w0TH, g_w0TH);
    cudaGetSymbolAddress((void**)&p_w0TL, g_w0TL);
    cudaGetSymbolAddress((void**)&p_w1TH, g_w1TH);
    cudaGetSymbolAddress((void**)&p_w1TL, g_w1TL);
    cudaGetSymbolAddress((void**)&p_bw0TH, g_bw0TH);
    cudaGetSymbolAddress((void**)&p_bw0TL, g_bw0TL);
    cudaGetSymbolAddress((void**)&p_bw1TH, g_bw1TH);
    cudaGetSymbolAddress((void**)&p_bw1TL, g_bw1TL);
    cudaGetSymbolAddress((void**)&p_wqTH, g_wqTH);
    cudaGetSymbolAddress((void**)&p_wqTL, g_wqTL);
    cudaGetSymbolAddress((void**)&p_biasTH, g_biasTH);
    cudaGetSymbolAddress((void**)&p_biasTL, g_biasTL);

    cudaFuncSetAttribute(gemm_mma, cudaFuncAttributeMaxDynamicSharedMemorySize, TCSMEM);
    cudaFuncSetAttribute(uvt_build, cudaFuncAttributeMaxDynamicSharedMemorySize, 131072);

    bool full = ((size_t)out_size >= OUT_TOTAL);
    float* out0     = out + OUT0_OFF;
    float* out_al   = full ? out + ALPHA_OFF : p_al;
    float* out_W    = full ? out + W_OFF     : p_W_fb;
    float* out_keys = full ? out + KEYS_OFF  : p_keys_fb;

    dim3 t328(32, 8);

    // ---- operand prep (packs + splits)
    split_kernel<<<(NPOOL * DPOOL / 4 + 255) / 256, 256>>>(pool, p_poolH, p_poolL,
                                                           NPOOL * DPOOL / 4);
    pack_wk<<<256, 256>>>(W_K, p_WkTH, p_WkTL);
    uvt_build<<<dim3(32, 4), 256, 131072>>>(pool, p_UVtH, p_UVtL);
    split_kernel<<<128, 256>>>(x, p_xH, p_xL, BATCH * DMODEL / 4);
    tsplit<<<dim3(32, 16), t328>>>(A_w0, HIDW, DMODEL, HIDW, p_w0TH, p_w0TL, DMODEL);
    tsplit<<<dim3(8, 32), t328>>>(A_w1, DA, HIDW, DA, p_w1TH, p_w1TL, HIDW);
    tsplit<<<dim3(32, 8), t328>>>(B_w0, HIDW, DA, HIDW, p_bw0TH, p_bw0TL, DA);
    tsplit<<<dim3(16, 32), t328>>>(B_w1, DMODEL, HIDW, DMODEL, p_bw1TH, p_bw1TL, HIDW);
    for (int a = 0; a < NASP; a++)
        tsplit<<<dim3(2, 8), t328>>>(W_Q + (size_t)a * DA * DK, DK, DA, DK,
                                     p_wqTH + (size_t)a * DK * DA,
                                     p_wqTL + (size_t)a * DK * DA, DA);
    tsplit<<<dim3(8, 64), t328>>>(pool + 4096, DPOOL, NPOOL, DB,
                                  p_biasTH, p_biasTL, NPOOL);

    // keys = pool @ W_K (HMMA, split-K=4): M=2048, N=256, K=4608
    gemm_mma<<<dim3(2, 16, 4), 256, TCSMEM>>>(p_poolH, p_poolL, p_WkTH, p_WkTL,
                                              nullptr, p_kpart, DPOOL, DPOOL / 4,
                                              256, (long long)NPOOL * 256, 0);
    reduce4_kernel<<<(NPOOL * 256 / 4 + 255) / 256, 256>>>(p_kpart, out_keys,
                                                           NPOOL * 256 / 4, NPOOL * 256);

    // A-MLP (HMMA): g1 = gelu(x@A_w0+b0); hA = g1@A_w1+b1
    gemm_mma<<<dim3(8, 2), 256, TCSMEM>>>(p_xH, p_xL, p_w0TH, p_w0TL,
                                          A_b0, p_g1, DMODEL, DMODEL, HIDW, 0, 1);
    split_kernel<<<256, 256>>>(p_g1, p_g1H, p_g1L, BATCH * HIDW / 4);
    gemm_mma<<<dim3(2, 2), 256, TCSMEM>>>(p_g1H, p_g1L, p_w1TH, p_w1TL,
                                          A_b1, p_hA, HIDW, HIDW, DA, 0, 0);
    split_kernel<<<64, 256>>>(p_hA, p_hAH, p_hAL, BATCH * DA / 4);

    // queries (HMMA): M=256, N=256, K=256
    gemm_mma<<<dim3(2, 2), 256, TCSMEM>>>(p_hAH, p_hAL, p_wqTH, p_wqTL,
                                          nullptr, p_q, DA, DA, DA, 0, 0);
    qnorm_kernel<<<BATCH, 128>>>(p_q, logits, p_qw);
    split_kernel<<<64, 256>>>(p_qw, p_qwH, p_qwL, BATCH * DA / 4);
    knorm_kernel<<<NPOOL, 128>>>(out_keys, p_kH, p_kL);

    // scores = qw @ k_norm^T (HMMA): M=256, N=2048, K=256
    gemm_mma<<<dim3(16, 2), 256, TCSMEM>>>(p_qwH, p_qwL, p_kH, p_kL,
                                           nullptr, p_sc, DA, DA, NPOOL, 0, 0);
    alpha_kernel<<<BATCH, 256>>>(p_sc, tau, p_al, out_al);
    split_kernel<<<512, 256>>>(p_al, p_alH, p_alL, BATCH * NPOOL / 4);

    // b_assembled (HMMA): M=256, N=256, K=2048
    gemm_mma<<<dim3(2, 2), 256, TCSMEM>>>(p_alH, p_alL, p_biasTH, p_biasTL,
                                          b_base, p_bt, NPOOL, NPOOL, DB, 0, 0);

    // W_assembled = alpha @ UV + W_base (HMMA): M=256, N=65536, K=2048
    gemm_mma<<<dim3(512, 2), 256, TCSMEM>>>(p_alH, p_alL, p_UVtH, p_UVtL,
                                            W_base, out_W, NPOOL, NPOOL, 65536, 0, 0);

    ht_kernel<<<BATCH, 256>>>(out_W, p_hA, p_ht);
    ln_kernel<<<BATCH, 256>>>(p_hA, p_ht, p_bt, gamma, ln_scale, ln_bias, p_hmid);
    split_kernel<<<64, 256>>>(p_hmid, p_hmH, p_hmL, BATCH * DA / 4);

    // B-MLP (HMMA): mid1 = gelu(hmid@B_w0+b0); output = mid1@B_w1+b1
    gemm_mma<<<dim3(8, 2), 256, TCSMEM>>>(p_hmH, p_hmL, p_bw0TH, p_bw0TL,
                                          B_b0, p_mid1, DA, DA, HIDW, 0, 1);
    split_kernel<<<256, 256>>>(p_mid1, p_m1H, p_m1L, BATCH * HIDW / 4);
    gemm_mma<<<dim3(4, 2), 256, TCSMEM>>>(p_m1H, p_m1L, p_bw1TH, p_bw1TL,
                                          B_b1, out0, HIDW, HIDW, DMODEL, 0, 0);
}